// round 8
// baseline (speedup 1.0000x reference)
#include <cuda_runtime.h>
#include <cuda_bf16.h>
#include <cstdint>

#define L    1024
#define CZ   128
#define NTC  8     // m-tiles (128-wide) -> PartC slots
#define NTR  16    // l-tiles (64-wide)  -> PartR slots

// ---------------- scratch ----------------
__device__ float g_PartC[(size_t)NTC * L * CZ];  // [bx][l][c] 4MB
__device__ float g_PartR[(size_t)NTR * L * CZ];  // [by][m][c] 8MB
__device__ float g_maskC[L];
__device__ float g_maskR[L];
__device__ float g_ssc[L * CZ];
__device__ float g_ssr[L * CZ];
__device__ float g_u[CZ];
__device__ float g_v[CZ];

// ---------------- helpers ----------------
__device__ __forceinline__ void cp16(uint32_t dst, const void* src) {
  asm volatile("cp.async.cg.shared.global [%0], [%1], 16;" :: "r"(dst), "l"(src));
}
__device__ __forceinline__ void cp_commit() { asm volatile("cp.async.commit_group;"); }
__device__ __forceinline__ uint32_t f2tf(float x) {
  uint32_t r; asm("cvt.rna.tf32.f32 %0, %1;" : "=r"(r) : "f"(x)); return r;
}
__device__ __forceinline__ void ldsm_x4(uint32_t& r0, uint32_t& r1, uint32_t& r2,
                                        uint32_t& r3, uint32_t addr) {
  asm volatile("ldmatrix.sync.aligned.m8n8.x4.shared.b16 {%0,%1,%2,%3}, [%4];"
               : "=r"(r0), "=r"(r1), "=r"(r2), "=r"(r3) : "r"(addr));
}

// ---------------- mask sums ----------------
__global__ void k_masksums(const float* __restrict__ mask) {
  __shared__ float red[2][256];
  int i = blockIdx.x, tid = threadIdx.x;
  float sc = 0.f, sr = 0.f;
  for (int j = tid; j < L; j += 256) {
    sc += mask[(size_t)i * L + j];
    sr += mask[(size_t)j * L + i];
  }
  red[0][tid] = sc; red[1][tid] = sr;
  __syncthreads();
  for (int s = 128; s > 0; s >>= 1) {
    if (tid < s) { red[0][tid] += red[0][tid + s]; red[1][tid] += red[1][tid + s]; }
    __syncthreads();
  }
  if (tid == 0) { g_maskC[i] = red[0][0]; g_maskR[i] = red[1][0]; }
}

// ---------------- prep: u = ln_b@w1^T + b1, v = ln_g@w1^T ----------------
__global__ void k_prep(const float* __restrict__ w1, const float* __restrict__ b1,
                       const float* __restrict__ ln_g, const float* __restrict__ ln_b) {
  int d = threadIdx.x;
  float u = b1[d], v = 0.f;
  for (int c = 0; c < CZ; c++) {
    float w = w1[d * CZ + c];
    u += ln_b[c] * w;
    v += ln_g[c] * w;
  }
  g_u[d] = u; g_v[d] = v;
}

// ---------------- stage 1: tile 64l x 128m, cp.async pipelined ----------------
__global__ __launch_bounds__(256, 1) void k_stage1(
    const float* __restrict__ s_z, const float* __restrict__ mask,
    const float* __restrict__ ln_g, const float* __restrict__ w1) {
  extern __shared__ char smem_raw[];
  __nv_bfloat16* sW  = (__nv_bfloat16*)smem_raw;      // [128][136] W~ = g*w1 (bf16)
  __nv_bfloat16* sAb = sW + 128 * 136;                // [64][136] z bf16 for MMA
  float* sZf   = (float*)(sAb + 64 * 136);            // [2][64][132] fp32 staging
  float* sMask = sZf + 2 * 64 * 132;                  // [64][132] mask tile (64l x 128m)
  float* sS    = sMask + 64 * 132;                    // [256] stat partials (sum)
  float* sS2   = sS + 256;                            // [256] (sumsq)
  float* sMu   = sS2 + 256;                           // [64]
  float* sRs   = sMu + 64;                            // [64]
  float* sU    = sRs + 64;                            // [128]
  float* sV    = sU + 128;                            // [128]
  float* sRow  = sV + 128;                            // [128]

  const int tid = threadIdx.x, lane = tid & 31, warp = tid >> 5;
  const int g = lane >> 2, q = lane & 3;
  const int wm = warp >> 1, wn = warp & 1;            // 4 x 2 warps, tile 16 x 64
  const int bx = blockIdx.x, by = blockIdx.y;
  const int m0 = bx * 128, l0 = by * 64;
  const int arow = wm * 16;

  // init: sW = bf16(w1 * g), u/v, mask tile, sRow=0
  for (int i = tid; i < 128 * 128; i += 256) {
    int d = i >> 7, c = i & 127;
    sW[d * 136 + c] = __float2bfloat16(w1[i] * ln_g[c]);
  }
  if (tid < 128) { sU[tid] = g_u[tid]; sV[tid] = g_v[tid]; sRow[tid] = 0.f; }
  for (int i = tid; i < 64 * 32; i += 256) {
    int r = i >> 5, c4 = (i & 31) << 2;
    float4 mv = *(const float4*)(mask + (size_t)(l0 + r) * L + m0 + c4);
    *(float4*)(sMask + r * 132 + c4) = mv;
  }

  const uint32_t aB = (uint32_t)__cvta_generic_to_shared(sAb);
  const uint32_t wB = (uint32_t)__cvta_generic_to_shared(sW);
  const uint32_t zB = (uint32_t)__cvta_generic_to_shared(sZf);
  const uint32_t aAddrBase =
      aB + (uint32_t)(((arow + (lane & 15)) * 136 + ((lane >> 4) << 3)) * 2);
  const uint32_t bRow  = wn * 64 + ((lane >> 4) << 3) + (lane & 7);
  const uint32_t bAddrBase = wB + (uint32_t)((bRow * 136 + (((lane >> 3) & 1) << 3)) * 2);

  // pack/stat/copy mapping: 4 threads per row (consecutive-lane rows -> no bank conflicts)
  const int prow = tid & 63, pqt = tid >> 6;

  auto issue = [&](int mi, int buf) {
    const float* src = s_z + ((size_t)(l0 + prow) * L + (m0 + mi)) * CZ + pqt * 32;
    uint32_t dst = zB + (uint32_t)((buf * 64 * 132 + prow * 132 + pqt * 32) * 4);
    #pragma unroll
    for (int j = 0; j < 8; j++) cp16(dst + j * 16, src + j * 4);
    cp_commit();
  };

  float colAcc[8][4];
  #pragma unroll
  for (int b = 0; b < 8; b++)
    #pragma unroll
    for (int c = 0; c < 4; c++) colAcc[b][c] = 0.f;

  issue(0, 0);

  for (int mi = 0; mi < 128; mi++) {
    const int buf = mi & 1;
    if (mi < 127) {
      issue(mi + 1, buf ^ 1);
      asm volatile("cp.async.wait_group 1;");
    } else {
      asm volatile("cp.async.wait_group 0;");
    }
    __syncthreads();  // barA: staging[buf] ready; prior pass fully done

    // ---- pack fp32 -> bf16 + stat partials (no shuffles) ----
    {
      const float* zr = sZf + buf * (64 * 132) + prow * 132 + pqt * 32;
      float s = 0.f, s2 = 0.f;
      uint32_t pk[16];
      #pragma unroll
      for (int j = 0; j < 8; j++) {
        float4 v = *(const float4*)(zr + j * 4);
        __nv_bfloat162 p0 = __floats2bfloat162_rn(v.x, v.y);
        __nv_bfloat162 p1 = __floats2bfloat162_rn(v.z, v.w);
        pk[2 * j]     = *(uint32_t*)&p0;
        pk[2 * j + 1] = *(uint32_t*)&p1;
        s  += v.x + v.y + v.z + v.w;
        s2 += v.x * v.x + v.y * v.y + v.z * v.z + v.w * v.w;
      }
      uint4* dst = (uint4*)(sAb + prow * 136 + pqt * 32);
      #pragma unroll
      for (int jj = 0; jj < 4; jj++)
        dst[jj] = make_uint4(pk[4 * jj], pk[4 * jj + 1], pk[4 * jj + 2], pk[4 * jj + 3]);
      sS[tid] = s; sS2[tid] = s2;   // tid == pqt*64 + prow
    }
    __syncthreads();  // barB

    // stat combine (runs on 2 warps, overlaps others' MMA start)
    if (tid < 64) {
      float s  = sS[tid] + sS[tid + 64] + sS[tid + 128] + sS[tid + 192];
      float s2 = sS2[tid] + sS2[tid + 64] + sS2[tid + 128] + sS2[tid + 192];
      float mu  = s * (1.f / 128.f);
      float var = fmaf(s2, 1.f / 128.f, -mu * mu);
      sMu[tid] = mu;
      sRs[tid] = rsqrtf(var + 1e-5f);
    }

    // ---- MMA: h[64x128] = sAb @ sW^T ----
    float acc[8][4];
    #pragma unroll
    for (int b = 0; b < 8; b++)
      #pragma unroll
      for (int c = 0; c < 4; c++) acc[b][c] = 0.f;

    #pragma unroll
    for (int ks = 0; ks < 8; ks++) {
      const uint32_t kByte = (uint32_t)(ks * 16 * 2);
      uint32_t a0, a1, a2, a3;
      ldsm_x4(a0, a1, a2, a3, aAddrBase + kByte);
      #pragma unroll
      for (int p = 0; p < 4; p++) {
        uint32_t b0, b1, b2, b3;
        ldsm_x4(b0, b1, b2, b3, bAddrBase + kByte + (uint32_t)(p * 16 * 136 * 2));
        asm volatile(
          "mma.sync.aligned.m16n8k16.row.col.f32.bf16.bf16.f32 "
          "{%0,%1,%2,%3}, {%4,%5,%6,%7}, {%8,%9}, {%0,%1,%2,%3};\n"
          : "+f"(acc[2*p][0]), "+f"(acc[2*p][1]), "+f"(acc[2*p][2]), "+f"(acc[2*p][3])
          : "r"(a0), "r"(a1), "r"(a2), "r"(a3), "r"(b0), "r"(b1));
        asm volatile(
          "mma.sync.aligned.m16n8k16.row.col.f32.bf16.bf16.f32 "
          "{%0,%1,%2,%3}, {%4,%5,%6,%7}, {%8,%9}, {%0,%1,%2,%3};\n"
          : "+f"(acc[2*p+1][0]), "+f"(acc[2*p+1][1]), "+f"(acc[2*p+1][2]), "+f"(acc[2*p+1][3])
          : "r"(a0), "r"(a1), "r"(a2), "r"(a3), "r"(b2), "r"(b3));
      }
    }
    __syncthreads();  // barC: sMu/sRs visible; sRow zeroed state stable

    // ---- epilogue: h = rs*acc + (u - mu*rs*v), relu, *mask; reductions ----
    const int row0 = arow + g, row1 = arow + g + 8;
    float mu0 = sMu[row0], rs0 = sRs[row0];
    float mu1 = sMu[row1], rs1 = sRs[row1];
    float mk0 = sMask[row0 * 132 + mi];
    float mk1 = sMask[row1 * 132 + mi];
    float c0 = -mu0 * rs0, c1 = -mu1 * rs1;
    float rsum[16];
    #pragma unroll
    for (int nb = 0; nb < 8; nb++) {
      const int col = wn * 64 + nb * 8 + q * 2;
      float u0 = sU[col], v0 = sV[col], u1 = sU[col + 1], v1 = sV[col + 1];
      float h0 = fmaxf(fmaf(rs0, acc[nb][0], fmaf(c0, v0, u0)), 0.f) * mk0;
      float h1 = fmaxf(fmaf(rs0, acc[nb][1], fmaf(c0, v1, u1)), 0.f) * mk0;
      float h2 = fmaxf(fmaf(rs1, acc[nb][2], fmaf(c1, v0, u0)), 0.f) * mk1;
      float h3 = fmaxf(fmaf(rs1, acc[nb][3], fmaf(c1, v1, u1)), 0.f) * mk1;
      colAcc[nb][0] += h0; colAcc[nb][1] += h1;
      colAcc[nb][2] += h2; colAcc[nb][3] += h3;
      rsum[nb * 2]     = h0 + h2;
      rsum[nb * 2 + 1] = h1 + h3;
    }
    #pragma unroll
    for (int off = 4; off < 32; off <<= 1) {
      #pragma unroll
      for (int i2 = 0; i2 < 16; i2++)
        rsum[i2] += __shfl_xor_sync(0xffffffffu, rsum[i2], off);
    }
    if (lane < 4) {
      #pragma unroll
      for (int nb = 0; nb < 8; nb++) {
        atomicAdd(&sRow[wn * 64 + nb * 8 + lane * 2    ], rsum[nb * 2]);
        atomicAdd(&sRow[wn * 64 + nb * 8 + lane * 2 + 1], rsum[nb * 2 + 1]);
      }
    }
    __syncthreads();  // barD: row sums complete
    if (tid < 128) {
      g_PartR[((size_t)by * L + (m0 + mi)) * CZ + tid] = sRow[tid];
      sRow[tid] = 0.f;
    }
  }

  // ---- write column partials (slot = bx) ----
  #pragma unroll
  for (int nb = 0; nb < 8; nb++) {
    const int col = wn * 64 + nb * 8 + q * 2;
    const int r0 = arow + g, r1 = r0 + 8;
    size_t base = (size_t)bx * L * CZ;
    *(float2*)(g_PartC + base + (size_t)(l0 + r0) * CZ + col) =
        make_float2(colAcc[nb][0], colAcc[nb][1]);
    *(float2*)(g_PartC + base + (size_t)(l0 + r1) * CZ + col) =
        make_float2(colAcc[nb][2], colAcc[nb][3]);
  }
}

// ---------------- stage 2: reduce partials, apply w2/b2, normalize ----------------
__global__ __launch_bounds__(256) void k_stage2(const float* __restrict__ w2,
                                                const float* __restrict__ b2) {
  extern __shared__ float w2s[];          // [128][132]
  __shared__ float sv[2][128];
  const int tid = threadIdx.x;
  const int half = tid >> 7, d = tid & 127;

  for (int i = tid; i < 128 * 128; i += 256) {
    int r = i >> 7, c = i & 127;
    w2s[r * 132 + c] = w2[i];
  }
  const float bd = b2[d];
  const float* P = half ? g_PartR : g_PartC;
  float* O = half ? g_ssr : g_ssc;
  const float* M = half ? g_maskR : g_maskC;
  const int nsl = half ? NTR : NTC;
  __syncthreads();

  for (int ii = 0; ii < 2; ii++) {
    const int i = blockIdx.x * 2 + ii;
    float a = 0.f;
    for (int t = 0; t < nsl; t++) a += P[((size_t)t * L + i) * CZ + d];
    if (ii) __syncthreads();
    sv[half][d] = a;
    __syncthreads();
    float m = M[i];
    const float4* wr = (const float4*)(w2s + d * 132);
    const float4* s4 = (const float4*)sv[half];
    float d0 = 0.f, d1 = 0.f, d2 = 0.f, d3 = 0.f;
    #pragma unroll
    for (int c = 0; c < 32; c++) {
      float4 wv = wr[c];
      float4 vv = s4[c];
      d0 = fmaf(vv.x, wv.x, d0);
      d1 = fmaf(vv.y, wv.y, d1);
      d2 = fmaf(vv.z, wv.z, d2);
      d3 = fmaf(vv.w, wv.w, d3);
    }
    O[i * CZ + d] = ((d0 + d1) + (d2 + d3) + bd * m) / fmaxf(m, 1.f);
  }
}

// ---------------- stage 3: out = cat @ wc^T + bc, tf32, pipelined ----------------
__global__ __launch_bounds__(256) void k_stage3(
    const float* __restrict__ s_s_in, const float* __restrict__ wc,
    const float* __restrict__ bc, float* __restrict__ out) {
  extern __shared__ float sm3[];
  float* sA3 = sm3;                 // [2][64][68]
  float* sB3 = sm3 + 2 * 64 * 68;   // [2][64][68]
  const uint32_t aBase = (uint32_t)__cvta_generic_to_shared(sA3);
  const uint32_t bBase = (uint32_t)__cvta_generic_to_shared(sB3);

  const int tid = threadIdx.x, lane = tid & 31, warp = tid >> 5;
  const int g = lane >> 2, q = lane & 3;
  const int wm = warp >> 1, wn = warp & 1;          // 4 x 2 warps, tile 16x32
  const int d0 = blockIdx.x * 64, t0 = blockIdx.y * 64;

  const int cr = tid >> 2, cseg = tid & 3;

  auto issue = [&](int kc, int buf) {
    const float* srcA; int strideA, koffA;
    if (kc < 2)      { srcA = g_ssc;  strideA = 128;  koffA = kc * 64; }
    else if (kc < 4) { srcA = g_ssr;  strideA = 128;  koffA = (kc - 2) * 64; }
    else             { srcA = s_s_in; strideA = 1024; koffA = (kc - 4) * 64; }
    const float* sa = srcA + (size_t)(t0 + cr) * strideA + koffA + cseg * 16;
    const float* sb = wc + (size_t)(d0 + cr) * 1280 + kc * 64 + cseg * 16;
    uint32_t da = aBase + (uint32_t)(buf * 4352 + cr * 68 + cseg * 16) * 4;
    uint32_t db = bBase + (uint32_t)(buf * 4352 + cr * 68 + cseg * 16) * 4;
    #pragma unroll
    for (int j = 0; j < 4; j++) { cp16(da + j * 16, sa + j * 4); cp16(db + j * 16, sb + j * 4); }
    cp_commit();
  };

  float acc[4][4];
  #pragma unroll
  for (int b = 0; b < 4; b++)
    #pragma unroll
    for (int c = 0; c < 4; c++) acc[b][c] = 0.f;

  issue(0, 0);

  for (int kc = 0; kc < 20; kc++) {
    const int buf = kc & 1;
    if (kc + 1 < 20) {
      issue(kc + 1, buf ^ 1);
      asm volatile("cp.async.wait_group 1;");
    } else {
      asm volatile("cp.async.wait_group 0;");
    }
    __syncthreads();

    const float* A = sA3 + buf * 4352;
    const float* B = sB3 + buf * 4352;
    const int R = wm * 16;
    #pragma unroll
    for (int ks = 0; ks < 8; ks++) {
      const int k0 = ks * 8;
      uint32_t a0 = f2tf(A[(R + g    ) * 68 + k0 + q    ]);
      uint32_t a1 = f2tf(A[(R + g + 8) * 68 + k0 + q    ]);
      uint32_t a2 = f2tf(A[(R + g    ) * 68 + k0 + q + 4]);
      uint32_t a3 = f2tf(A[(R + g + 8) * 68 + k0 + q + 4]);
      #pragma unroll
      for (int nb = 0; nb < 4; nb++) {
        const int n = wn * 32 + nb * 8 + g;
        uint32_t b0 = f2tf(B[n * 68 + k0 + q    ]);
        uint32_t b1 = f2tf(B[n * 68 + k0 + q + 4]);
        asm volatile(
          "mma.sync.aligned.m16n8k8.row.col.f32.tf32.tf32.f32 "
          "{%0,%1,%2,%3}, {%4,%5,%6,%7}, {%8,%9}, {%0,%1,%2,%3};\n"
          : "+f"(acc[nb][0]), "+f"(acc[nb][1]), "+f"(acc[nb][2]), "+f"(acc[nb][3])
          : "r"(a0), "r"(a1), "r"(a2), "r"(a3), "r"(b0), "r"(b1));
      }
    }
    __syncthreads();
  }

  const int r0 = t0 + wm * 16 + g;
  #pragma unroll
  for (int nb = 0; nb < 4; nb++) {
    const int c = d0 + wn * 32 + nb * 8 + q * 2;
    float bc0 = bc[c], bc1 = bc[c + 1];
    *(float2*)(out + (size_t)r0 * L + c)       = make_float2(acc[nb][0] + bc0, acc[nb][1] + bc1);
    *(float2*)(out + (size_t)(r0 + 8) * L + c) = make_float2(acc[nb][2] + bc0, acc[nb][3] + bc1);
  }
}

// ---------------- launch ----------------
extern "C" void kernel_launch(void* const* d_in, const int* in_sizes, int n_in,
                              void* d_out, int out_size) {
  const float* s_z    = (const float*)d_in[0];
  const float* s_s_in = (const float*)d_in[1];
  const float* pmask  = (const float*)d_in[2];
  const float* ln_g   = (const float*)d_in[3];
  const float* ln_b   = (const float*)d_in[4];
  const float* w1     = (const float*)d_in[5];
  const float* b1     = (const float*)d_in[6];
  const float* w2     = (const float*)d_in[7];
  const float* b2     = (const float*)d_in[8];
  const float* wc     = (const float*)d_in[9];
  const float* bc     = (const float*)d_in[10];
  float* out = (float*)d_out;

  // stage1 smem: sW 34816 + sAb 17408 + sZf 67584 + sMask 33792 + sS/sS2 2048
  //              + (64+64+128+128+128)*4 = 157696
  const int smem1 = 157696;
  const int smem2 = 128 * 132 * 4;        // 67584
  const int smem3 = 2 * 2 * 64 * 68 * 4;  // 69632
  cudaFuncSetAttribute(k_stage1, cudaFuncAttributeMaxDynamicSharedMemorySize, smem1);
  cudaFuncSetAttribute(k_stage2, cudaFuncAttributeMaxDynamicSharedMemorySize, smem2);
  cudaFuncSetAttribute(k_stage3, cudaFuncAttributeMaxDynamicSharedMemorySize, smem3);

  k_masksums<<<L, 256>>>(pmask);
  k_prep<<<1, CZ>>>(w1, b1, ln_g, ln_b);
  k_stage1<<<dim3(8, 16), 256, smem1>>>(s_z, pmask, ln_g, w1);
  k_stage2<<<512, 256, smem2>>>(w2, b2);
  k_stage3<<<dim3(16, 16), 256, smem3>>>(s_s_in, wc, bc, out);
}

// round 11
// speedup vs baseline: 1.5383x; 1.5383x over previous
#include <cuda_runtime.h>
#include <cuda_bf16.h>
#include <cstdint>

#define L    1024
#define CZ   128
#define NTC  8     // m-tiles (128-wide) -> PartC slots
#define NTR  32    // l-tile halves     -> PartR slots

#if defined(__CUDA_ARCH__) && (defined(__CUDA_ARCH_FEAT_SM103_ALL) || \
    defined(__CUDA_ARCH_FEAT_SM100_ALL) || defined(__CUDA_ARCH_SPECIFIC__))
#define TC_OK 1
#else
#define TC_OK 0
#endif

// ---------------- scratch ----------------
__device__ float g_PartC[(size_t)NTC * L * CZ];  // [bx][l][c] 4MB
__device__ float g_PartR[(size_t)NTR * L * CZ];  // [by*2+half][m][c] 16MB
__device__ float g_maskC[L];
__device__ float g_maskR[L];
__device__ float g_ssc[L * CZ];
__device__ float g_ssr[L * CZ];
__device__ float g_u[CZ];
__device__ float g_v[CZ];

// ---------------- helpers ----------------
__device__ __forceinline__ void cp16(uint32_t dst, const void* src) {
  asm volatile("cp.async.cg.shared.global [%0], [%1], 16;" :: "r"(dst), "l"(src));
}
__device__ __forceinline__ void cp_commit() { asm volatile("cp.async.commit_group;"); }
__device__ __forceinline__ uint32_t f2tf(float x) {
  uint32_t r; asm("cvt.rna.tf32.f32 %0, %1;" : "=r"(r) : "f"(x)); return r;
}
__device__ __forceinline__ uint32_t smem_u32(const void* p) {
  return (uint32_t)__cvta_generic_to_shared(p);
}
__device__ __forceinline__ uint32_t sw128(uint32_t b) { return b ^ ((b >> 3) & 0x70); }

#if TC_OK
__device__ __forceinline__ uint32_t elect1() {
  uint32_t pred;
  asm volatile("{\n\t.reg .pred p;\n\telect.sync _|p, 0xFFFFFFFF;\n\t"
               "selp.b32 %0, 1, 0, p;\n\t}" : "=r"(pred));
  return pred;
}
#define TC_ALLOC(sm, n)  asm volatile("tcgen05.alloc.cta_group::1.sync.aligned.shared::cta.b32 [%0], %1;" :: "r"(sm), "r"(n) : "memory")
#define TC_RELINQ()      asm volatile("tcgen05.relinquish_alloc_permit.cta_group::1.sync.aligned;")
#define TC_DEALLOC(t, n) asm volatile("tcgen05.dealloc.cta_group::1.sync.aligned.b32 %0, %1;" :: "r"(t), "r"(n))
#define TC_COMMIT(mb)    asm volatile("tcgen05.commit.cta_group::1.mbarrier::arrive::one.shared::cluster.b64 [%0];" :: "r"(mb) : "memory")
#define TC_WAIT_LD()     asm volatile("tcgen05.wait::ld.sync.aligned;" ::: "memory")
#define TC_FENCE_B()     asm volatile("tcgen05.fence::before_thread_sync;" ::: "memory")
#define TC_FENCE_A()     asm volatile("tcgen05.fence::after_thread_sync;" ::: "memory")
#define MBAR_INIT(mb, c) asm volatile("mbarrier.init.shared.b64 [%0], %1;" :: "r"(mb), "r"(c) : "memory")

__device__ __forceinline__ void mbar_wait(uint32_t mb, uint32_t parity) {
  asm volatile(
      "{\n\t.reg .pred P1;\n\t"
      "WL_%=:\n\t"
      "mbarrier.try_wait.parity.acquire.cta.shared::cta.b64 P1, [%0], %1, 0x989680;\n\t"
      "@P1 bra.uni WD_%=;\n\t"
      "bra.uni WL_%=;\n\t"
      "WD_%=:\n\t}" :: "r"(mb), "r"(parity) : "memory");
}
__device__ __forceinline__ void mma_f16_ss(uint32_t d, uint64_t a, uint64_t b,
                                           uint32_t idesc, bool accum) {
  uint32_t e = accum ? 1u : 0u, z = 0u;
  asm volatile(
      "{\n\t.reg .pred p;\n\tsetp.ne.u32 p, %5, 0;\n\t"
      "tcgen05.mma.cta_group::1.kind::f16 [%0], %1, %2, %3, {%4,%4,%4,%4}, p;\n\t}"
      :: "r"(d), "l"(a), "l"(b), "r"(idesc), "r"(z), "r"(e) : "memory");
}
__device__ __forceinline__ void ldtm_x32(uint32_t* r, uint32_t tmem) {
  asm volatile(
      "tcgen05.ld.sync.aligned.32x32b.x32.b32 "
      "{%0,%1,%2,%3,%4,%5,%6,%7,%8,%9,%10,%11,%12,%13,%14,%15,"
      "%16,%17,%18,%19,%20,%21,%22,%23,%24,%25,%26,%27,%28,%29,%30,%31}, [%32];"
      : "=r"(r[0]), "=r"(r[1]), "=r"(r[2]), "=r"(r[3]), "=r"(r[4]), "=r"(r[5]),
        "=r"(r[6]), "=r"(r[7]), "=r"(r[8]), "=r"(r[9]), "=r"(r[10]), "=r"(r[11]),
        "=r"(r[12]), "=r"(r[13]), "=r"(r[14]), "=r"(r[15]), "=r"(r[16]), "=r"(r[17]),
        "=r"(r[18]), "=r"(r[19]), "=r"(r[20]), "=r"(r[21]), "=r"(r[22]), "=r"(r[23]),
        "=r"(r[24]), "=r"(r[25]), "=r"(r[26]), "=r"(r[27]), "=r"(r[28]), "=r"(r[29]),
        "=r"(r[30]), "=r"(r[31])
      : "r"(tmem));
}

// SMEM descriptor: SW128, version=1 (Blackwell), SBO=64, LBO=1
static constexpr uint64_t DESC_BASE =
    (uint64_t(2) << 61) | (uint64_t(1) << 46) | (uint64_t(64) << 32) | (uint64_t(1) << 16);
__device__ __forceinline__ uint64_t make_desc(uint32_t smaddr) {
  return DESC_BASE | ((uint64_t)(smaddr >> 4) & 0x3FFF);
}
// idesc: f32 acc, bf16 x bf16, M=128, N=64, K-major both
static constexpr uint32_t IDESC =
    (1u << 4) | (1u << 7) | (1u << 10) | ((64u >> 3) << 17) | ((128u >> 4) << 24);
#endif  // TC_OK

// blocked SW128 byte offsets (rows x 128 bf16 cols, 8x64 atoms, atom cols stacked)
__device__ __forceinline__ uint32_t wByte(int r, int c) {  // 128-row tile (W~)
  return sw128((uint32_t)((((r >> 3) + (c >> 6) * 16) << 10) + ((r & 7) << 7) + ((c & 63) << 1)));
}
__device__ __forceinline__ uint32_t zByte(int r, int c) {  // 64-row tile (z)
  return sw128((uint32_t)((((r >> 3) + (c >> 6) * 8) << 10) + ((r & 7) << 7) + ((c & 63) << 1)));
}

// ---------------- mask sums ----------------
__global__ void k_masksums(const float* __restrict__ mask) {
  __shared__ float red[2][256];
  int i = blockIdx.x, tid = threadIdx.x;
  float sc = 0.f, sr = 0.f;
  for (int j = tid; j < L; j += 256) {
    sc += mask[(size_t)i * L + j];
    sr += mask[(size_t)j * L + i];
  }
  red[0][tid] = sc; red[1][tid] = sr;
  __syncthreads();
  for (int s = 128; s > 0; s >>= 1) {
    if (tid < s) { red[0][tid] += red[0][tid + s]; red[1][tid] += red[1][tid + s]; }
    __syncthreads();
  }
  if (tid == 0) { g_maskC[i] = red[0][0]; g_maskR[i] = red[1][0]; }
}

// ---------------- prep ----------------
__global__ void k_prep(const float* __restrict__ w1, const float* __restrict__ b1,
                       const float* __restrict__ ln_g, const float* __restrict__ ln_b) {
  int d = threadIdx.x;
  float u = b1[d], v = 0.f;
  for (int c = 0; c < CZ; c++) {
    float w = w1[d * CZ + c];
    u += ln_b[c] * w;
    v += ln_g[c] * w;
  }
  g_u[d] = u; g_v[d] = v;
}

// ---------------- stage 1: tcgen05 D[d,pair] = W~ @ z^T ----------------
__global__ __launch_bounds__(256, 1) void k_stage1(
    const float* __restrict__ s_z, const float* __restrict__ mask,
    const float* __restrict__ ln_g, const float* __restrict__ w1) {
#if TC_OK
  extern __shared__ char smem_raw[];
  __nv_bfloat16* sW  = (__nv_bfloat16*)smem_raw;          //  32768 B  W~ blocked
  __nv_bfloat16* sZb = (__nv_bfloat16*)(smem_raw + 32768);//  2x16384  z bf16 blocked
  float* sZf   = (float*)(smem_raw + 65536);              //  2x(64*132*4)=67584 staging
  float* sMask = (float*)(smem_raw + 133120);             //  64*132*4 = 33792
  float* sS    = (float*)(smem_raw + 166912);             //  1024
  float* sS2   = (float*)(smem_raw + 167936);             //  1024
  float* sRsMu = (float*)(smem_raw + 168960);             //  1024 (rs, -mu*rs)
  uint32_t* sT = (uint32_t*)(smem_raw + 169984);          //  tmem ptr
  const uint32_t mbarA[2] = { smem_u32(smem_raw + 170000), smem_u32(smem_raw + 170008) };

  const int tid = threadIdx.x, lane = tid & 31, warp = tid >> 5;
  const int bx = blockIdx.x, by = blockIdx.y;
  const int m0 = bx * 128, l0 = by * 64;
  const int dd = (warp & 3) * 32 + lane;    // this thread's output channel
  const int half = warp >> 2;               // which 32 pair-cols

  const uint32_t zfB = smem_u32(sZf);

  // ---- init ----
  if (warp == 0) { TC_ALLOC(smem_u32(sT), 128); TC_RELINQ(); }
  if (tid == 0) { MBAR_INIT(mbarA[0], 1); MBAR_INIT(mbarA[1], 1); }
  for (int i = tid; i < 128 * 128; i += 256) {
    int d = i >> 7, c = i & 127;
    *(__nv_bfloat16*)((char*)sW + wByte(d, c)) = __float2bfloat16(w1[i] * ln_g[c]);
  }
  for (int i = tid; i < 64 * 32; i += 256) {
    int r = i >> 5, c4 = (i & 31) << 2;
    float4 mv = *(const float4*)(mask + (size_t)(l0 + r) * L + m0 + c4);
    *(float4*)(sMask + r * 132 + c4) = mv;
  }
  const float uD = g_u[dd], vD = g_v[dd];
  __syncthreads();
  const uint32_t tmem = sT[0];

  // staging copy mapping: row = tid&63 (pair l), seg = tid>>6 (32 floats)
  const int prow = tid & 63, pseg = tid >> 6;
  auto issue = [&](int mi, int buf) {
    const float* src = s_z + ((size_t)(l0 + prow) * L + (m0 + mi)) * CZ + pseg * 32;
    uint32_t dst = zfB + (uint32_t)((buf * 64 * 132 + prow * 132 + pseg * 32) * 4);
    #pragma unroll
    for (int j = 0; j < 8; j++) cp16(dst + j * 16, src + j * 4);
    cp_commit();
  };

  float colAcc[32];
  #pragma unroll
  for (int j = 0; j < 32; j++) colAcc[j] = 0.f;

  const uint64_t wDesc = make_desc(smem_u32(sW));

  issue(0, 0);

  for (int mi = 0; mi < 128; mi++) {
    const int buf = mi & 1;
    if (mi < 127) {
      issue(mi + 1, buf ^ 1);
      asm volatile("cp.async.wait_group 1;");
    } else {
      asm volatile("cp.async.wait_group 0;");
    }
    __syncthreads();  // staging[buf] ready; zb[buf] free; D[buf] free

    // ---- pack fp32 -> bf16 blocked/swizzled + stat partials ----
    {
      const float* zr = sZf + buf * (64 * 132) + prow * 132 + pseg * 32;
      char* zbB = (char*)(sZb + buf * (64 * 128));
      float s = 0.f, s2 = 0.f;
      #pragma unroll
      for (int j = 0; j < 4; j++) {
        float4 v0 = *(const float4*)(zr + j * 8);
        float4 v1 = *(const float4*)(zr + j * 8 + 4);
        __nv_bfloat162 p0 = __floats2bfloat162_rn(v0.x, v0.y);
        __nv_bfloat162 p1 = __floats2bfloat162_rn(v0.z, v0.w);
        __nv_bfloat162 p2 = __floats2bfloat162_rn(v1.x, v1.y);
        __nv_bfloat162 p3 = __floats2bfloat162_rn(v1.z, v1.w);
        *(uint4*)(zbB + zByte(prow, pseg * 32 + j * 8)) =
            make_uint4(*(uint32_t*)&p0, *(uint32_t*)&p1, *(uint32_t*)&p2, *(uint32_t*)&p3);
        s  += v0.x + v0.y + v0.z + v0.w + v1.x + v1.y + v1.z + v1.w;
        s2 += v0.x*v0.x + v0.y*v0.y + v0.z*v0.z + v0.w*v0.w
            + v1.x*v1.x + v1.y*v1.y + v1.z*v1.z + v1.w*v1.w;
      }
      sS[tid] = s; sS2[tid] = s2;
      TC_FENCE_B();
    }
    __syncthreads();  // zb[buf], partials ready

    // stat combine -> sRsMu[buf] (consumed by epilogue next iteration)
    if (tid < 64) {
      float s  = sS[tid] + sS[tid + 64] + sS[tid + 128] + sS[tid + 192];
      float s2 = sS2[tid] + sS2[tid + 64] + sS2[tid + 128] + sS2[tid + 192];
      float mu  = s * (1.f / 128.f);
      float var = fmaf(s2, 1.f / 128.f, -mu * mu);
      float rs  = rsqrtf(var + 1e-5f);
      sRsMu[(buf * 64 + tid) * 2]     = rs;
      sRsMu[(buf * 64 + tid) * 2 + 1] = -mu * rs;
    }

    // ---- issue MMA(mi) into D[buf] ----
    if (warp == 0) {
      TC_FENCE_A();
      if (elect1()) {
        uint64_t zDesc = make_desc(smem_u32(sZb + buf * (64 * 128)));
        #pragma unroll
        for (int kc = 0; kc < 8; kc++) {
          uint64_t aOff = (uint64_t)((kc & 3) * 2 + (kc >> 2) * 1024);
          uint64_t bOff = (uint64_t)((kc & 3) * 2 + (kc >> 2) * 512);
          mma_f16_ss(tmem + buf * 64, wDesc + aOff, zDesc + bOff, IDESC, kc > 0);
        }
        TC_COMMIT(mbarA[buf]);
      }
    }

    // ---- epilogue for pass mi-1 (reads D[buf^1]) ----
    if (mi > 0) {
      const int pj = mi - 1, pb = buf ^ 1;
      mbar_wait(mbarA[pb], (uint32_t)((pj >> 1) & 1));
      TC_FENCE_A();
      uint32_t dr[32];
      ldtm_x32(dr, tmem + pb * 64 + half * 32);
      TC_WAIT_LD();
      float rsum = 0.f;
      #pragma unroll
      for (int j = 0; j < 32; j++) {
        int lc = half * 32 + j;
        float rs   = sRsMu[(pb * 64 + lc) * 2];
        float murs = sRsMu[(pb * 64 + lc) * 2 + 1];
        float mk   = sMask[lc * 132 + pj];
        float h = fmaf(rs, __uint_as_float(dr[j]), fmaf(murs, vD, uD));
        h = fmaxf(h, 0.f) * mk;
        colAcc[j] += h;
        rsum += h;
      }
      g_PartR[((size_t)(by * 2 + half) * L + (m0 + pj)) * CZ + dd] = rsum;
      TC_FENCE_B();
    }
  }

  // final epilogue: pass 127, D[1]
  {
    const int pj = 127, pb = 1;
    mbar_wait(mbarA[pb], (uint32_t)((pj >> 1) & 1));
    TC_FENCE_A();
    uint32_t dr[32];
    ldtm_x32(dr, tmem + pb * 64 + half * 32);
    TC_WAIT_LD();
    float rsum = 0.f;
    #pragma unroll
    for (int j = 0; j < 32; j++) {
      int lc = half * 32 + j;
      float rs   = sRsMu[(pb * 64 + lc) * 2];
      float murs = sRsMu[(pb * 64 + lc) * 2 + 1];
      float mk   = sMask[lc * 132 + pj];
      float h = fmaf(rs, __uint_as_float(dr[j]), fmaf(murs, vD, uD));
      h = fmaxf(h, 0.f) * mk;
      colAcc[j] += h;
      rsum += h;
    }
    g_PartR[((size_t)(by * 2 + half) * L + (m0 + pj)) * CZ + dd] = rsum;
    TC_FENCE_B();
  }

  // ---- write column partials: slot = bx ----
  #pragma unroll
  for (int j = 0; j < 32; j++) {
    int l = l0 + half * 32 + j;
    g_PartC[((size_t)bx * L + l) * CZ + dd] = colAcc[j];
  }

  __syncthreads();
  if (warp == 0) TC_DEALLOC(tmem, 128);

#else  // ---------------- fallback (generic PTX target only; correct, slow) ----------------
  extern __shared__ char smem_raw[];
  float* sWf  = (float*)smem_raw;             // [128][128] fp32 W~
  float* sZ1  = (float*)(smem_raw + 65536);   // [64][128]
  float* sSt  = (float*)(smem_raw + 98304);   // [64][2] rs, -mu*rs

  const int tid = threadIdx.x;
  const int bx = blockIdx.x, by = blockIdx.y;
  const int m0 = bx * 128, l0 = by * 64;
  const int d = tid & 127, lh = tid >> 7;

  for (int i = tid; i < 128 * 128; i += 256) {
    int r = i >> 7, c = i & 127;
    sWf[i] = w1[i] * ln_g[c];
  }
  const float uD = g_u[d], vD = g_v[d];
  float colAcc[32];
  #pragma unroll
  for (int j = 0; j < 32; j++) colAcc[j] = 0.f;
  __syncthreads();

  for (int mi = 0; mi < 128; mi++) {
    for (int i = tid; i < 64 * 32; i += 256) {
      int r = i >> 5, c4 = (i & 31) << 2;
      float4 v = *(const float4*)(s_z + ((size_t)(l0 + r) * L + (m0 + mi)) * CZ + c4);
      *(float4*)(sZ1 + r * 128 + c4) = v;
    }
    __syncthreads();
    if (tid < 64) {
      float s = 0.f, s2 = 0.f;
      for (int c = 0; c < 128; c++) {
        float v = sZ1[tid * 128 + c];
        s += v; s2 += v * v;
      }
      float mu  = s * (1.f / 128.f);
      float var = fmaf(s2, 1.f / 128.f, -mu * mu);
      float rs  = rsqrtf(var + 1e-5f);
      sSt[tid * 2] = rs; sSt[tid * 2 + 1] = -mu * rs;
    }
    __syncthreads();
    float rsum = 0.f;
    for (int j = 0; j < 32; j++) {
      int l = lh * 32 + j;
      float dot = 0.f;
      for (int c = 0; c < 128; c++)
        dot = fmaf(__bfloat162float(__float2bfloat16(sZ1[l * 128 + c])),
                   __bfloat162float(__float2bfloat16(sWf[d * 128 + c])), dot);
      float h = fmaf(sSt[l * 2], dot, fmaf(sSt[l * 2 + 1], vD, uD));
      h = fmaxf(h, 0.f) * mask[(size_t)(l0 + l) * L + (m0 + mi)];
      colAcc[j] += h; rsum += h;
    }
    g_PartR[((size_t)(by * 2 + lh) * L + (m0 + mi)) * CZ + d] = rsum;
    __syncthreads();
  }
  for (int j = 0; j < 32; j++)
    g_PartC[((size_t)bx * L + (l0 + lh * 32 + j)) * CZ + d] = colAcc[j];
#endif
}

// ---------------- stage 2 ----------------
__global__ __launch_bounds__(256) void k_stage2(const float* __restrict__ w2,
                                                const float* __restrict__ b2) {
  extern __shared__ float w2s[];          // [128][132]
  __shared__ float sv[2][128];
  const int tid = threadIdx.x;
  const int half = tid >> 7, d = tid & 127;

  for (int i = tid; i < 128 * 128; i += 256) {
    int r = i >> 7, c = i & 127;
    w2s[r * 132 + c] = w2[i];
  }
  const float bd = b2[d];
  const float* P = half ? g_PartR : g_PartC;
  float* O = half ? g_ssr : g_ssc;
  const float* M = half ? g_maskR : g_maskC;
  const int nsl = half ? NTR : NTC;
  __syncthreads();

  for (int ii = 0; ii < 2; ii++) {
    const int i = blockIdx.x * 2 + ii;
    float a = 0.f;
    for (int t = 0; t < nsl; t++) a += P[((size_t)t * L + i) * CZ + d];
    if (ii) __syncthreads();
    sv[half][d] = a;
    __syncthreads();
    float m = M[i];
    const float4* wr = (const float4*)(w2s + d * 132);
    const float4* s4 = (const float4*)sv[half];
    float d0 = 0.f, d1 = 0.f, d2 = 0.f, d3 = 0.f;
    #pragma unroll
    for (int c = 0; c < 32; c++) {
      float4 wv = wr[c];
      float4 vv = s4[c];
      d0 = fmaf(vv.x, wv.x, d0);
      d1 = fmaf(vv.y, wv.y, d1);
      d2 = fmaf(vv.z, wv.z, d2);
      d3 = fmaf(vv.w, wv.w, d3);
    }
    O[i * CZ + d] = ((d0 + d1) + (d2 + d3) + bd * m) / fmaxf(m, 1.f);
  }
}

// ---------------- stage 3: out = cat @ wc^T + bc, tf32, pipelined ----------------
__global__ __launch_bounds__(256) void k_stage3(
    const float* __restrict__ s_s_in, const float* __restrict__ wc,
    const float* __restrict__ bc, float* __restrict__ out) {
  extern __shared__ float sm3[];
  float* sA3 = sm3;                 // [2][64][68]
  float* sB3 = sm3 + 2 * 64 * 68;   // [2][64][68]
  const uint32_t aBase = smem_u32(sA3);
  const uint32_t bBase = smem_u32(sB3);

  const int tid = threadIdx.x, lane = tid & 31, warp = tid >> 5;
  const int g = lane >> 2, q = lane & 3;
  const int wm = warp >> 1, wn = warp & 1;
  const int d0 = blockIdx.x * 64, t0 = blockIdx.y * 64;

  const int cr = tid >> 2, cseg = tid & 3;

  auto issue = [&](int kc, int buf) {
    const float* srcA; int strideA, koffA;
    if (kc < 2)      { srcA = g_ssc;  strideA = 128;  koffA = kc * 64; }
    else if (kc < 4) { srcA = g_ssr;  strideA = 128;  koffA = (kc - 2) * 64; }
    else             { srcA = s_s_in; strideA = 1024; koffA = (kc - 4) * 64; }
    const float* sa = srcA + (size_t)(t0 + cr) * strideA + koffA + cseg * 16;
    const float* sb = wc + (size_t)(d0 + cr) * 1280 + kc * 64 + cseg * 16;
    uint32_t da = aBase + (uint32_t)(buf * 4352 + cr * 68 + cseg * 16) * 4;
    uint32_t db = bBase + (uint32_t)(buf * 4352 + cr * 68 + cseg * 16) * 4;
    #pragma unroll
    for (int j = 0; j < 4; j++) { cp16(da + j * 16, sa + j * 4); cp16(db + j * 16, sb + j * 4); }
    cp_commit();
  };

  float acc[4][4];
  #pragma unroll
  for (int b = 0; b < 4; b++)
    #pragma unroll
    for (int c = 0; c < 4; c++) acc[b][c] = 0.f;

  issue(0, 0);

  for (int kc = 0; kc < 20; kc++) {
    const int buf = kc & 1;
    if (kc + 1 < 20) {
      issue(kc + 1, buf ^ 1);
      asm volatile("cp.async.wait_group 1;");
    } else {
      asm volatile("cp.async.wait_group 0;");
    }
    __syncthreads();

    const float* A = sA3 + buf * 4352;
    const float* B = sB3 + buf * 4352;
    const int R = wm * 16;
    #pragma unroll
    for (int ks = 0; ks < 8; ks++) {
      const int k0 = ks * 8;
      uint32_t a0 = f2tf(A[(R + g    ) * 68 + k0 + q    ]);
      uint32_t a1 = f2tf(A[(R + g + 8) * 68 + k0 + q    ]);
      uint32_t a2 = f2tf(A[(R + g    ) * 68 + k0 + q + 4]);
      uint32_t a3 = f2tf(A[(R + g + 8) * 68 + k0 + q + 4]);
      #pragma unroll
      for (int nb = 0; nb < 4; nb++) {
        const int n = wn * 32 + nb * 8 + g;
        uint32_t b0 = f2tf(B[n * 68 + k0 + q    ]);
        uint32_t b1 = f2tf(B[n * 68 + k0 + q + 4]);
        asm volatile(
          "mma.sync.aligned.m16n8k8.row.col.f32.tf32.tf32.f32 "
          "{%0,%1,%2,%3}, {%4,%5,%6,%7}, {%8,%9}, {%0,%1,%2,%3};\n"
          : "+f"(acc[nb][0]), "+f"(acc[nb][1]), "+f"(acc[nb][2]), "+f"(acc[nb][3])
          : "r"(a0), "r"(a1), "r"(a2), "r"(a3), "r"(b0), "r"(b1));
      }
    }
    __syncthreads();
  }

  const int r0 = t0 + wm * 16 + g;
  #pragma unroll
  for (int nb = 0; nb < 4; nb++) {
    const int c = d0 + wn * 32 + nb * 8 + q * 2;
    float bc0 = bc[c], bc1 = bc[c + 1];
    *(float2*)(out + (size_t)r0 * L + c)       = make_float2(acc[nb][0] + bc0, acc[nb][1] + bc1);
    *(float2*)(out + (size_t)(r0 + 8) * L + c) = make_float2(acc[nb][2] + bc0, acc[nb][3] + bc1);
  }
}

// ---------------- launch ----------------
extern "C" void kernel_launch(void* const* d_in, const int* in_sizes, int n_in,
                              void* d_out, int out_size) {
  const float* s_z    = (const float*)d_in[0];
  const float* s_s_in = (const float*)d_in[1];
  const float* pmask  = (const float*)d_in[2];
  const float* ln_g   = (const float*)d_in[3];
  const float* ln_b   = (const float*)d_in[4];
  const float* w1     = (const float*)d_in[5];
  const float* b1     = (const float*)d_in[6];
  const float* w2     = (const float*)d_in[7];
  const float* b2     = (const float*)d_in[8];
  const float* wc     = (const float*)d_in[9];
  const float* bc     = (const float*)d_in[10];
  float* out = (float*)d_out;

  const int smem1 = 170048;
  const int smem2 = 128 * 132 * 4;        // 67584
  const int smem3 = 2 * 2 * 64 * 68 * 4;  // 69632
  cudaFuncSetAttribute(k_stage1, cudaFuncAttributeMaxDynamicSharedMemorySize, smem1);
  cudaFuncSetAttribute(k_stage2, cudaFuncAttributeMaxDynamicSharedMemorySize, smem2);
  cudaFuncSetAttribute(k_stage3, cudaFuncAttributeMaxDynamicSharedMemorySize, smem3);

  k_masksums<<<L, 256>>>(pmask);
  k_prep<<<1, CZ>>>(w1, b1, ln_g, ln_b);
  k_stage1<<<dim3(8, 16), 256, smem1>>>(s_z, pmask, ln_g, w1);
  k_stage2<<<512, 256, smem2>>>(w2, b2);
  k_stage3<<<dim3(16, 16), 256, smem3>>>(s_s_in, wc, bc, out);
}

// round 14
// speedup vs baseline: 1.5399x; 1.0010x over previous
#include <cuda_runtime.h>
#include <cuda_bf16.h>
#include <cstdint>

#define L    1024
#define CZ   128
#define NTC  8     // m-tiles (128-wide) -> PartC slots
#define NTR  16    // l-tiles (64-wide)  -> PartR slots (quarters merged)

#if defined(__CUDA_ARCH__) && (defined(__CUDA_ARCH_FEAT_SM103_ALL) || \
    defined(__CUDA_ARCH_FEAT_SM100_ALL) || defined(__CUDA_ARCH_SPECIFIC__))
#define TC_OK 1
#else
#define TC_OK 0
#endif

// ---------------- scratch ----------------
__device__ float g_PartC[(size_t)NTC * L * CZ];  // [bx][l][c] 4MB
__device__ float g_PartR[(size_t)NTR * L * CZ];  // [by][m][c] 8MB
__device__ float g_maskC[L];
__device__ float g_maskR[L];
__device__ float g_ssc[L * CZ];
__device__ float g_ssr[L * CZ];
__device__ float g_u[CZ];
__device__ float g_v[CZ];

// ---------------- helpers ----------------
__device__ __forceinline__ void cp16(uint32_t dst, const void* src) {
  asm volatile("cp.async.cg.shared.global [%0], [%1], 16;" :: "r"(dst), "l"(src));
}
__device__ __forceinline__ void cp_commit() { asm volatile("cp.async.commit_group;"); }
__device__ __forceinline__ uint32_t f2tf(float x) {
  uint32_t r; asm("cvt.rna.tf32.f32 %0, %1;" : "=r"(r) : "f"(x)); return r;
}
__device__ __forceinline__ uint32_t smem_u32(const void* p) {
  return (uint32_t)__cvta_generic_to_shared(p);
}
__device__ __forceinline__ uint32_t sw128(uint32_t b) { return b ^ ((b >> 3) & 0x70); }

#if TC_OK
__device__ __forceinline__ uint32_t elect1() {
  uint32_t pred;
  asm volatile("{\n\t.reg .pred p;\n\telect.sync _|p, 0xFFFFFFFF;\n\t"
               "selp.b32 %0, 1, 0, p;\n\t}" : "=r"(pred));
  return pred;
}
#define TC_ALLOC(sm, n)  asm volatile("tcgen05.alloc.cta_group::1.sync.aligned.shared::cta.b32 [%0], %1;" :: "r"(sm), "r"(n) : "memory")
#define TC_RELINQ()      asm volatile("tcgen05.relinquish_alloc_permit.cta_group::1.sync.aligned;")
#define TC_DEALLOC(t, n) asm volatile("tcgen05.dealloc.cta_group::1.sync.aligned.b32 %0, %1;" :: "r"(t), "r"(n))
#define TC_COMMIT(mb)    asm volatile("tcgen05.commit.cta_group::1.mbarrier::arrive::one.shared::cluster.b64 [%0];" :: "r"(mb) : "memory")
#define TC_WAIT_LD()     asm volatile("tcgen05.wait::ld.sync.aligned;" ::: "memory")
#define TC_FENCE_B()     asm volatile("tcgen05.fence::before_thread_sync;" ::: "memory")
#define TC_FENCE_A()     asm volatile("tcgen05.fence::after_thread_sync;" ::: "memory")
#define MBAR_INIT(mb, c) asm volatile("mbarrier.init.shared.b64 [%0], %1;" :: "r"(mb), "r"(c) : "memory")

__device__ __forceinline__ void mbar_wait(uint32_t mb, uint32_t parity) {
  asm volatile(
      "{\n\t.reg .pred P1;\n\t"
      "WL_%=:\n\t"
      "mbarrier.try_wait.parity.acquire.cta.shared::cta.b64 P1, [%0], %1, 0x989680;\n\t"
      "@P1 bra.uni WD_%=;\n\t"
      "bra.uni WL_%=;\n\t"
      "WD_%=:\n\t}" :: "r"(mb), "r"(parity) : "memory");
}
__device__ __forceinline__ void mma_f16_ss(uint32_t d, uint64_t a, uint64_t b,
                                           uint32_t idesc, bool accum) {
  uint32_t e = accum ? 1u : 0u, z = 0u;
  asm volatile(
      "{\n\t.reg .pred p;\n\tsetp.ne.u32 p, %5, 0;\n\t"
      "tcgen05.mma.cta_group::1.kind::f16 [%0], %1, %2, %3, {%4,%4,%4,%4}, p;\n\t}"
      :: "r"(d), "l"(a), "l"(b), "r"(idesc), "r"(z), "r"(e) : "memory");
}
__device__ __forceinline__ void ldtm_x16(uint32_t* r, uint32_t tmem) {
  asm volatile(
      "tcgen05.ld.sync.aligned.32x32b.x16.b32 "
      "{%0,%1,%2,%3,%4,%5,%6,%7,%8,%9,%10,%11,%12,%13,%14,%15}, [%16];"
      : "=r"(r[0]), "=r"(r[1]), "=r"(r[2]), "=r"(r[3]), "=r"(r[4]), "=r"(r[5]),
        "=r"(r[6]), "=r"(r[7]), "=r"(r[8]), "=r"(r[9]), "=r"(r[10]), "=r"(r[11]),
        "=r"(r[12]), "=r"(r[13]), "=r"(r[14]), "=r"(r[15])
      : "r"(tmem));
}

static constexpr uint64_t DESC_BASE =
    (uint64_t(2) << 61) | (uint64_t(1) << 46) | (uint64_t(64) << 32) | (uint64_t(1) << 16);
__device__ __forceinline__ uint64_t make_desc(uint32_t smaddr) {
  return DESC_BASE | ((uint64_t)(smaddr >> 4) & 0x3FFF);
}
// idesc: f32 acc, bf16 x bf16, M=128, N=64, K-major both
static constexpr uint32_t IDESC =
    (1u << 4) | (1u << 7) | (1u << 10) | ((64u >> 3) << 17) | ((128u >> 4) << 24);
#endif  // TC_OK

// blocked SW128 byte offsets (rows x 128 bf16 cols, 8x64 atoms, atom cols stacked)
__device__ __forceinline__ uint32_t wByte(int r, int c) {  // 128-row tile (W~)
  return sw128((uint32_t)((((r >> 3) + (c >> 6) * 16) << 10) + ((r & 7) << 7) + ((c & 63) << 1)));
}
__device__ __forceinline__ uint32_t zByte(int r, int c) {  // 64-row tile (z)
  return sw128((uint32_t)((((r >> 3) + (c >> 6) * 8) << 10) + ((r & 7) << 7) + ((c & 63) << 1)));
}

// ---------------- mask sums ----------------
__global__ void k_masksums(const float* __restrict__ mask) {
  __shared__ float red[2][256];
  int i = blockIdx.x, tid = threadIdx.x;
  float sc = 0.f, sr = 0.f;
  for (int j = tid; j < L; j += 256) {
    sc += mask[(size_t)i * L + j];
    sr += mask[(size_t)j * L + i];
  }
  red[0][tid] = sc; red[1][tid] = sr;
  __syncthreads();
  for (int s = 128; s > 0; s >>= 1) {
    if (tid < s) { red[0][tid] += red[0][tid + s]; red[1][tid] += red[1][tid + s]; }
    __syncthreads();
  }
  if (tid == 0) { g_maskC[i] = red[0][0]; g_maskR[i] = red[1][0]; }
}

// ---------------- prep ----------------
__global__ void k_prep(const float* __restrict__ w1, const float* __restrict__ b1,
                       const float* __restrict__ ln_g, const float* __restrict__ ln_b) {
  int d = threadIdx.x;
  float u = b1[d], v = 0.f;
  for (int c = 0; c < CZ; c++) {
    float w = w1[d * CZ + c];
    u += ln_b[c] * w;
    v += ln_g[c] * w;
  }
  g_u[d] = u; g_v[d] = v;
}

// ---------------- stage 1: tcgen05 D[d,pair] = W~ @ z^T, 512 threads ----------------
__global__ __launch_bounds__(512, 1) void k_stage1(
    const float* __restrict__ s_z, const float* __restrict__ mask,
    const float* __restrict__ ln_g, const float* __restrict__ w1) {
#if TC_OK
  extern __shared__ char smem_raw[];
  __nv_bfloat16* sW  = (__nv_bfloat16*)smem_raw;            // 32768  W~ blocked
  __nv_bfloat16* sZb = (__nv_bfloat16*)(smem_raw + 32768);  // 2x16384 z bf16 blocked
  float* sZf   = (float*)(smem_raw + 65536);                // 2x(64*132*4)=67584 staging
  float* sMaskT= (float*)(smem_raw + 133120);               // [128 m][68 l] = 34816
  float* sS    = (float*)(smem_raw + 167936);               // 2048
  float* sS2   = (float*)(smem_raw + 169984);               // 2048
  float* sRsMu = (float*)(smem_raw + 172032);               // [2][64][2] = 1024
  float* sRowP = (float*)(smem_raw + 173056);               // [2][4][128] = 4096
  uint32_t* sT = (uint32_t*)(smem_raw + 177152);
  const uint32_t mbarA[2] = { smem_u32(smem_raw + 177160), smem_u32(smem_raw + 177168) };

  const int tid = threadIdx.x, lane = tid & 31, warp = tid >> 5;
  const int bx = blockIdx.x, by = blockIdx.y;
  const int m0 = bx * 128, l0 = by * 64;
  const int dsub = warp & 3, q4 = warp >> 2;    // subpartition / column quarter
  const int dd = dsub * 32 + lane;              // this thread's output channel

  const uint32_t zfB = smem_u32(sZf);

  // ---- init ----
  if (warp == 0) { TC_ALLOC(smem_u32(sT), 128); TC_RELINQ(); }
  if (tid == 0) { MBAR_INIT(mbarA[0], 1); MBAR_INIT(mbarA[1], 1); }
  for (int i = tid; i < 128 * 128; i += 512) {
    int d = i >> 7, c = i & 127;
    *(__nv_bfloat16*)((char*)sW + wByte(d, c)) = __float2bfloat16(w1[i] * ln_g[c]);
  }
  // mask tile transposed: sMaskT[m][l], stride 68
  for (int i = tid; i < 64 * 32; i += 512) {
    int r = i >> 5, c4 = (i & 31) << 2;
    float4 mv = *(const float4*)(mask + (size_t)(l0 + r) * L + m0 + c4);
    sMaskT[(c4 + 0) * 68 + r] = mv.x;
    sMaskT[(c4 + 1) * 68 + r] = mv.y;
    sMaskT[(c4 + 2) * 68 + r] = mv.z;
    sMaskT[(c4 + 3) * 68 + r] = mv.w;
  }
  const float uD = g_u[dd], vD = g_v[dd];
  __syncthreads();
  const uint32_t tmem = sT[0];

  // staging mapping: prow = (warp>>3)*32 + lane (all lanes distinct rows), seg = warp&7
  const int prow = (warp >> 3) * 32 + lane, pseg = warp & 7;
  auto issue = [&](int mi, int buf) {
    const float* src = s_z + ((size_t)(l0 + prow) * L + (m0 + mi)) * CZ + pseg * 16;
    uint32_t dst = zfB + (uint32_t)((buf * 64 * 132 + prow * 132 + pseg * 16) * 4);
    #pragma unroll
    for (int j = 0; j < 4; j++) cp16(dst + j * 16, src + j * 4);
    cp_commit();
  };

  float colAcc[16];
  #pragma unroll
  for (int j = 0; j < 16; j++) colAcc[j] = 0.f;

  const uint64_t wDesc = make_desc(smem_u32(sW));

  // epilogue for pass pj (D in buffer pb); accumulates colAcc, writes sRowP
  auto epilogue = [&](int pj, int pb) {
    mbar_wait(mbarA[pb], (uint32_t)((pj >> 1) & 1));
    TC_FENCE_A();
    uint32_t dr[16];
    ldtm_x16(dr, tmem + pb * 64 + q4 * 16);
    TC_WAIT_LD();
    float rsum = 0.f;
    #pragma unroll
    for (int h2 = 0; h2 < 2; h2++) {
      float4 rm[4];
      #pragma unroll
      for (int k = 0; k < 4; k++)
        rm[k] = *(const float4*)(sRsMu + (pb * 64 + q4 * 16 + h2 * 8) * 2 + k * 4);
      float4 mk0 = *(const float4*)(sMaskT + pj * 68 + q4 * 16 + h2 * 8);
      float4 mk1 = *(const float4*)(sMaskT + pj * 68 + q4 * 16 + h2 * 8 + 4);
      const float* rmf = (const float*)rm;
      const float* mkf = (const float*)&mk0;  // mk0,mk1 contiguous on stack? avoid: handle separately
      #pragma unroll
      for (int j = 0; j < 8; j++) {
        float rs   = rmf[2 * j];
        float murs = rmf[2 * j + 1];
        float mk   = (j < 4) ? ((const float*)&mk0)[j] : ((const float*)&mk1)[j - 4];
        float h = fmaf(rs, __uint_as_float(dr[h2 * 8 + j]), fmaf(murs, vD, uD));
        h = fmaxf(h, 0.f) * mk;
        colAcc[h2 * 8 + j] += h;
        rsum += h;
      }
    }
    sRowP[(pj & 1) * 512 + q4 * 128 + dd] = rsum;
    TC_FENCE_B();
  };
  // combine quarter row-sums of pass p -> g_PartR (after a barrier covering sRowP writes)
  auto combine = [&](int p) {
    if (tid < 128) {
      const float* rp = sRowP + (p & 1) * 512;
      float v = rp[tid] + rp[128 + tid] + rp[256 + tid] + rp[384 + tid];
      g_PartR[((size_t)by * L + (m0 + p)) * CZ + tid] = v;
    }
  };

  issue(0, 0);

  for (int mi = 0; mi < 128; mi++) {
    const int buf = mi & 1;
    if (mi < 127) {
      issue(mi + 1, buf ^ 1);
      asm volatile("cp.async.wait_group 1;");
    } else {
      asm volatile("cp.async.wait_group 0;");
    }
    __syncthreads();  // barA: staging[buf] ready; sRowP[mi&1] (pass mi-2) complete

    if (mi >= 2) combine(mi - 2);

    // ---- pack fp32 -> bf16 blocked/swizzled + stat partials ----
    {
      const float* zr = sZf + buf * (64 * 132) + prow * 132 + pseg * 16;
      char* zbB = (char*)(sZb + buf * (64 * 128));
      float4 v0 = *(const float4*)(zr);
      float4 v1 = *(const float4*)(zr + 4);
      float4 v2 = *(const float4*)(zr + 8);
      float4 v3 = *(const float4*)(zr + 12);
      __nv_bfloat162 p0 = __floats2bfloat162_rn(v0.x, v0.y);
      __nv_bfloat162 p1 = __floats2bfloat162_rn(v0.z, v0.w);
      __nv_bfloat162 p2 = __floats2bfloat162_rn(v1.x, v1.y);
      __nv_bfloat162 p3 = __floats2bfloat162_rn(v1.z, v1.w);
      __nv_bfloat162 p4 = __floats2bfloat162_rn(v2.x, v2.y);
      __nv_bfloat162 p5 = __floats2bfloat162_rn(v2.z, v2.w);
      __nv_bfloat162 p6 = __floats2bfloat162_rn(v3.x, v3.y);
      __nv_bfloat162 p7 = __floats2bfloat162_rn(v3.z, v3.w);
      *(uint4*)(zbB + zByte(prow, pseg * 16)) =
          make_uint4(*(uint32_t*)&p0, *(uint32_t*)&p1, *(uint32_t*)&p2, *(uint32_t*)&p3);
      *(uint4*)(zbB + zByte(prow, pseg * 16 + 8)) =
          make_uint4(*(uint32_t*)&p4, *(uint32_t*)&p5, *(uint32_t*)&p6, *(uint32_t*)&p7);
      float s  = (v0.x + v0.y + v0.z + v0.w) + (v1.x + v1.y + v1.z + v1.w)
               + (v2.x + v2.y + v2.z + v2.w) + (v3.x + v3.y + v3.z + v3.w);
      float s2 = (v0.x*v0.x + v0.y*v0.y + v0.z*v0.z + v0.w*v0.w)
               + (v1.x*v1.x + v1.y*v1.y + v1.z*v1.z + v1.w*v1.w)
               + (v2.x*v2.x + v2.y*v2.y + v2.z*v2.z + v2.w*v2.w)
               + (v3.x*v3.x + v3.y*v3.y + v3.z*v3.z + v3.w*v3.w);
      sS[tid] = s; sS2[tid] = s2;
      TC_FENCE_B();
    }
    __syncthreads();  // barB: zb[buf], partials ready

    // stat combine -> sRsMu[buf]
    if (tid < 64) {
      const int base = (tid >> 5) * 256 + (tid & 31);
      float s = 0.f, s2 = 0.f;
      #pragma unroll
      for (int sg = 0; sg < 8; sg++) { s += sS[base + sg * 32]; s2 += sS2[base + sg * 32]; }
      float mu  = s * (1.f / 128.f);
      float var = fmaf(s2, 1.f / 128.f, -mu * mu);
      float rs  = rsqrtf(var + 1e-5f);
      sRsMu[(buf * 64 + tid) * 2]     = rs;
      sRsMu[(buf * 64 + tid) * 2 + 1] = -mu * rs;
    }

    // ---- issue MMA(mi) into D[buf] ----
    if (warp == 0) {
      TC_FENCE_A();
      if (elect1()) {
        uint64_t zDesc = make_desc(smem_u32(sZb + buf * (64 * 128)));
        #pragma unroll
        for (int kc = 0; kc < 8; kc++) {
          uint64_t aOff = (uint64_t)((kc & 3) * 2 + (kc >> 2) * 1024);
          uint64_t bOff = (uint64_t)((kc & 3) * 2 + (kc >> 2) * 512);
          mma_f16_ss(tmem + buf * 64, wDesc + aOff, zDesc + bOff, IDESC, kc > 0);
        }
        TC_COMMIT(mbarA[buf]);
      }
    }

    // ---- epilogue for pass mi-1 ----
    if (mi > 0) epilogue(mi - 1, buf ^ 1);
  }

  __syncthreads();
  combine(126);
  epilogue(127, 1);
  __syncthreads();
  combine(127);

  // ---- write column partials: slot = bx; thread owns l = q4*16+j ----
  #pragma unroll
  for (int j = 0; j < 16; j++) {
    int l = l0 + q4 * 16 + j;
    g_PartC[((size_t)bx * L + l) * CZ + dd] = colAcc[j];
  }

  __syncthreads();
  if (warp == 0) TC_DEALLOC(tmem, 128);

#else  // ---------------- fallback (generic PTX target only; correct, slow) ----------------
  extern __shared__ char smem_raw[];
  float* sWf  = (float*)smem_raw;             // [128][128] fp32 W~
  float* sZ1  = (float*)(smem_raw + 65536);   // [64][128]
  float* sSt  = (float*)(smem_raw + 98304);   // [64][2]
  float* sRp  = (float*)(smem_raw + 99328);   // [4][128]

  const int tid = threadIdx.x;
  const int bx = blockIdx.x, by = blockIdx.y;
  const int m0 = bx * 128, l0 = by * 64;
  const int d = tid & 127, grp = tid >> 7;    // 4 groups of 16 l's

  for (int i = tid; i < 128 * 128; i += 512) {
    int c = i & 127;
    sWf[i] = w1[i] * ln_g[c];
  }
  const float uD = g_u[d], vD = g_v[d];
  float colAcc[16];
  #pragma unroll
  for (int j = 0; j < 16; j++) colAcc[j] = 0.f;
  __syncthreads();

  for (int mi = 0; mi < 128; mi++) {
    for (int i = tid; i < 64 * 32; i += 512) {
      int r = i >> 5, c4 = (i & 31) << 2;
      float4 v = *(const float4*)(s_z + ((size_t)(l0 + r) * L + (m0 + mi)) * CZ + c4);
      *(float4*)(sZ1 + r * 128 + c4) = v;
    }
    __syncthreads();
    if (tid < 64) {
      float s = 0.f, s2 = 0.f;
      for (int c = 0; c < 128; c++) {
        float v = sZ1[tid * 128 + c];
        s += v; s2 += v * v;
      }
      float mu  = s * (1.f / 128.f);
      float var = fmaf(s2, 1.f / 128.f, -mu * mu);
      float rs  = rsqrtf(var + 1e-5f);
      sSt[tid * 2] = rs; sSt[tid * 2 + 1] = -mu * rs;
    }
    __syncthreads();
    float rsum = 0.f;
    for (int j = 0; j < 16; j++) {
      int l = grp * 16 + j;
      float dot = 0.f;
      for (int c = 0; c < 128; c++)
        dot = fmaf(__bfloat162float(__float2bfloat16(sZ1[l * 128 + c])),
                   __bfloat162float(__float2bfloat16(sWf[d * 128 + c])), dot);
      float h = fmaf(sSt[l * 2], dot, fmaf(sSt[l * 2 + 1], vD, uD));
      h = fmaxf(h, 0.f) * mask[(size_t)(l0 + l) * L + (m0 + mi)];
      colAcc[j] += h; rsum += h;
    }
    sRp[grp * 128 + d] = rsum;
    __syncthreads();
    if (tid < 128)
      g_PartR[((size_t)by * L + (m0 + mi)) * CZ + tid] =
          sRp[tid] + sRp[128 + tid] + sRp[256 + tid] + sRp[384 + tid];
    __syncthreads();
  }
  for (int j = 0; j < 16; j++)
    g_PartC[((size_t)bx * L + (l0 + grp * 16 + j)) * CZ + d] = colAcc[j];
#endif
}

// ---------------- stage 2 ----------------
__global__ __launch_bounds__(256) void k_stage2(const float* __restrict__ w2,
                                                const float* __restrict__ b2) {
  extern __shared__ float w2s[];          // [128][132]
  __shared__ float sv[2][128];
  const int tid = threadIdx.x;
  const int half = tid >> 7, d = tid & 127;

  for (int i = tid; i < 128 * 128; i += 256) {
    int r = i >> 7, c = i & 127;
    w2s[r * 132 + c] = w2[i];
  }
  const float bd = b2[d];
  const float* P = half ? g_PartR : g_PartC;
  float* O = half ? g_ssr : g_ssc;
  const float* M = half ? g_maskR : g_maskC;
  const int nsl = half ? NTR : NTC;
  __syncthreads();

  for (int ii = 0; ii < 2; ii++) {
    const int i = blockIdx.x * 2 + ii;
    float a = 0.f;
    for (int t = 0; t < nsl; t++) a += P[((size_t)t * L + i) * CZ + d];
    if (ii) __syncthreads();
    sv[half][d] = a;
    __syncthreads();
    float m = M[i];
    const float4* wr = (const float4*)(w2s + d * 132);
    const float4* s4 = (const float4*)sv[half];
    float d0 = 0.f, d1 = 0.f, d2 = 0.f, d3 = 0.f;
    #pragma unroll
    for (int c = 0; c < 32; c++) {
      float4 wv = wr[c];
      float4 vv = s4[c];
      d0 = fmaf(vv.x, wv.x, d0);
      d1 = fmaf(vv.y, wv.y, d1);
      d2 = fmaf(vv.z, wv.z, d2);
      d3 = fmaf(vv.w, wv.w, d3);
    }
    O[i * CZ + d] = ((d0 + d1) + (d2 + d3) + bd * m) / fmaxf(m, 1.f);
  }
}

// ---------------- stage 3: out = cat @ wc^T + bc, tf32, pipelined ----------------
__global__ __launch_bounds__(256) void k_stage3(
    const float* __restrict__ s_s_in, const float* __restrict__ wc,
    const float* __restrict__ bc, float* __restrict__ out) {
  extern __shared__ float sm3[];
  float* sA3 = sm3;                 // [2][64][68]
  float* sB3 = sm3 + 2 * 64 * 68;   // [2][64][68]
  const uint32_t aBase = smem_u32(sA3);
  const uint32_t bBase = smem_u32(sB3);

  const int tid = threadIdx.x, lane = tid & 31, warp = tid >> 5;
  const int g = lane >> 2, q = lane & 3;
  const int wm = warp >> 1, wn = warp & 1;
  const int d0 = blockIdx.x * 64, t0 = blockIdx.y * 64;

  const int cr = tid >> 2, cseg = tid & 3;

  auto issue = [&](int kc, int buf) {
    const float* srcA; int strideA, koffA;
    if (kc < 2)      { srcA = g_ssc;  strideA = 128;  koffA = kc * 64; }
    else if (kc < 4) { srcA = g_ssr;  strideA = 128;  koffA = (kc - 2) * 64; }
    else             { srcA = s_s_in; strideA = 1024; koffA = (kc - 4) * 64; }
    const float* sa = srcA + (size_t)(t0 + cr) * strideA + koffA + cseg * 16;
    const float* sb = wc + (size_t)(d0 + cr) * 1280 + kc * 64 + cseg * 16;
    uint32_t da = aBase + (uint32_t)(buf * 4352 + cr * 68 + cseg * 16) * 4;
    uint32_t db = bBase + (uint32_t)(buf * 4352 + cr * 68 + cseg * 16) * 4;
    #pragma unroll
    for (int j = 0; j < 4; j++) { cp16(da + j * 16, sa + j * 4); cp16(db + j * 16, sb + j * 4); }
    cp_commit();
  };

  float acc[4][4];
  #pragma unroll
  for (int b = 0; b < 4; b++)
    #pragma unroll
    for (int c = 0; c < 4; c++) acc[b][c] = 0.f;

  issue(0, 0);

  for (int kc = 0; kc < 20; kc++) {
    const int buf = kc & 1;
    if (kc + 1 < 20) {
      issue(kc + 1, buf ^ 1);
      asm volatile("cp.async.wait_group 1;");
    } else {
      asm volatile("cp.async.wait_group 0;");
    }
    __syncthreads();

    const float* A = sA3 + buf * 4352;
    const float* B = sB3 + buf * 4352;
    const int R = wm * 16;
    #pragma unroll
    for (int ks = 0; ks < 8; ks++) {
      const int k0 = ks * 8;
      uint32_t a0 = f2tf(A[(R + g    ) * 68 + k0 + q    ]);
      uint32_t a1 = f2tf(A[(R + g + 8) * 68 + k0 + q    ]);
      uint32_t a2 = f2tf(A[(R + g    ) * 68 + k0 + q + 4]);
      uint32_t a3 = f2tf(A[(R + g + 8) * 68 + k0 + q + 4]);
      #pragma unroll
      for (int nb = 0; nb < 4; nb++) {
        const int n = wn * 32 + nb * 8 + g;
        uint32_t b0 = f2tf(B[n * 68 + k0 + q    ]);
        uint32_t b1 = f2tf(B[n * 68 + k0 + q + 4]);
        asm volatile(
          "mma.sync.aligned.m16n8k8.row.col.f32.tf32.tf32.f32 "
          "{%0,%1,%2,%3}, {%4,%5,%6,%7}, {%8,%9}, {%0,%1,%2,%3};\n"
          : "+f"(acc[nb][0]), "+f"(acc[nb][1]), "+f"(acc[nb][2]), "+f"(acc[nb][3])
          : "r"(a0), "r"(a1), "r"(a2), "r"(a3), "r"(b0), "r"(b1));
      }
    }
    __syncthreads();
  }

  const int r0 = t0 + wm * 16 + g;
  #pragma unroll
  for (int nb = 0; nb < 4; nb++) {
    const int c = d0 + wn * 32 + nb * 8 + q * 2;
    float bc0 = bc[c], bc1 = bc[c + 1];
    *(float2*)(out + (size_t)r0 * L + c)       = make_float2(acc[nb][0] + bc0, acc[nb][1] + bc1);
    *(float2*)(out + (size_t)(r0 + 8) * L + c) = make_float2(acc[nb][2] + bc0, acc[nb][3] + bc1);
  }
}

// ---------------- launch ----------------
extern "C" void kernel_launch(void* const* d_in, const int* in_sizes, int n_in,
                              void* d_out, int out_size) {
  const float* s_z    = (const float*)d_in[0];
  const float* s_s_in = (const float*)d_in[1];
  const float* pmask  = (const float*)d_in[2];
  const float* ln_g   = (const float*)d_in[3];
  const float* ln_b   = (const float*)d_in[4];
  const float* w1     = (const float*)d_in[5];
  const float* b1     = (const float*)d_in[6];
  const float* w2     = (const float*)d_in[7];
  const float* b2     = (const float*)d_in[8];
  const float* wc     = (const float*)d_in[9];
  const float* bc     = (const float*)d_in[10];
  float* out = (float*)d_out;

  const int smem1 = 177280;
  const int smem2 = 128 * 132 * 4;        // 67584
  const int smem3 = 2 * 2 * 64 * 68 * 4;  // 69632
  cudaFuncSetAttribute(k_stage1, cudaFuncAttributeMaxDynamicSharedMemorySize, smem1);
  cudaFuncSetAttribute(k_stage2, cudaFuncAttributeMaxDynamicSharedMemorySize, smem2);
  cudaFuncSetAttribute(k_stage3, cudaFuncAttributeMaxDynamicSharedMemorySize, smem3);

  k_masksums<<<L, 256>>>(pmask);
  k_prep<<<1, CZ>>>(w1, b1, ln_g, ln_b);
  k_stage1<<<dim3(8, 16), 512, smem1>>>(s_z, pmask, ln_g, w1);
  k_stage2<<<512, 256, smem2>>>(w2, b2);
  k_stage3<<<dim3(16, 16), 256, smem3>>>(s_s_in, wc, bc, out);
}

// round 17
// speedup vs baseline: 2.2081x; 1.4339x over previous
#include <cuda_runtime.h>
#include <cuda_bf16.h>
#include <cstdint>

#define L    1024
#define CZ   128
#define NTC  8     // m-tiles (128-wide) -> PartC slots
#define NTR  16    // l-tiles (64-wide)  -> PartR slots (quarters merged)

#if defined(__CUDA_ARCH__) && (defined(__CUDA_ARCH_FEAT_SM103_ALL) || \
    defined(__CUDA_ARCH_FEAT_SM100_ALL) || defined(__CUDA_ARCH_SPECIFIC__))
#define TC_OK 1
#else
#define TC_OK 0
#endif

// ---------------- scratch ----------------
__device__ float g_PartC[(size_t)NTC * L * CZ];  // [bx][l][c] 4MB
__device__ float g_PartR[(size_t)NTR * L * CZ];  // [by][m][c] 8MB
__device__ float g_maskC[L];
__device__ float g_maskR[L];
__device__ float g_ssc[L * CZ];
__device__ float g_ssr[L * CZ];
__device__ float g_u[CZ];
__device__ float g_v[CZ];

// ---------------- helpers ----------------
__device__ __forceinline__ void cp16(uint32_t dst, const void* src) {
  asm volatile("cp.async.cg.shared.global [%0], [%1], 16;" :: "r"(dst), "l"(src));
}
__device__ __forceinline__ void cp_commit() { asm volatile("cp.async.commit_group;"); }
__device__ __forceinline__ uint32_t f2tf(float x) {
  uint32_t r; asm("cvt.rna.tf32.f32 %0, %1;" : "=r"(r) : "f"(x)); return r;
}
__device__ __forceinline__ uint32_t smem_u32(const void* p) {
  return (uint32_t)__cvta_generic_to_shared(p);
}
__device__ __forceinline__ uint32_t sw128(uint32_t b) { return b ^ ((b >> 3) & 0x70); }

#if TC_OK
__device__ __forceinline__ uint32_t elect1() {
  uint32_t pred;
  asm volatile("{\n\t.reg .pred p;\n\telect.sync _|p, 0xFFFFFFFF;\n\t"
               "selp.b32 %0, 1, 0, p;\n\t}" : "=r"(pred));
  return pred;
}
#define TC_ALLOC(sm, n)  asm volatile("tcgen05.alloc.cta_group::1.sync.aligned.shared::cta.b32 [%0], %1;" :: "r"(sm), "r"(n) : "memory")
#define TC_RELINQ()      asm volatile("tcgen05.relinquish_alloc_permit.cta_group::1.sync.aligned;")
#define TC_DEALLOC(t, n) asm volatile("tcgen05.dealloc.cta_group::1.sync.aligned.b32 %0, %1;" :: "r"(t), "r"(n))
#define TC_COMMIT(mb)    asm volatile("tcgen05.commit.cta_group::1.mbarrier::arrive::one.shared::cluster.b64 [%0];" :: "r"(mb) : "memory")
#define TC_WAIT_LD()     asm volatile("tcgen05.wait::ld.sync.aligned;" ::: "memory")
#define TC_FENCE_B()     asm volatile("tcgen05.fence::before_thread_sync;" ::: "memory")
#define TC_FENCE_A()     asm volatile("tcgen05.fence::after_thread_sync;" ::: "memory")
#define MBAR_INIT(mb, c) asm volatile("mbarrier.init.shared.b64 [%0], %1;" :: "r"(mb), "r"(c) : "memory")

__device__ __forceinline__ void mbar_wait(uint32_t mb, uint32_t parity) {
  asm volatile(
      "{\n\t.reg .pred P1;\n\t"
      "WL_%=:\n\t"
      "mbarrier.try_wait.parity.acquire.cta.shared::cta.b64 P1, [%0], %1, 0x989680;\n\t"
      "@P1 bra.uni WD_%=;\n\t"
      "bra.uni WL_%=;\n\t"
      "WD_%=:\n\t}" :: "r"(mb), "r"(parity) : "memory");
}
__device__ __forceinline__ void mma_f16_ss(uint32_t d, uint64_t a, uint64_t b,
                                           uint32_t idesc, bool accum) {
  uint32_t e = accum ? 1u : 0u, z = 0u;
  asm volatile(
      "{\n\t.reg .pred p;\n\tsetp.ne.u32 p, %5, 0;\n\t"
      "tcgen05.mma.cta_group::1.kind::f16 [%0], %1, %2, %3, {%4,%4,%4,%4}, p;\n\t}"
      :: "r"(d), "l"(a), "l"(b), "r"(idesc), "r"(z), "r"(e) : "memory");
}
__device__ __forceinline__ void ldtm_x16(uint32_t* r, uint32_t tmem) {
  asm volatile(
      "tcgen05.ld.sync.aligned.32x32b.x16.b32 "
      "{%0,%1,%2,%3,%4,%5,%6,%7,%8,%9,%10,%11,%12,%13,%14,%15}, [%16];"
      : "=r"(r[0]), "=r"(r[1]), "=r"(r[2]), "=r"(r[3]), "=r"(r[4]), "=r"(r[5]),
        "=r"(r[6]), "=r"(r[7]), "=r"(r[8]), "=r"(r[9]), "=r"(r[10]), "=r"(r[11]),
        "=r"(r[12]), "=r"(r[13]), "=r"(r[14]), "=r"(r[15])
      : "r"(tmem));
}

static constexpr uint64_t DESC_BASE =
    (uint64_t(2) << 61) | (uint64_t(1) << 46) | (uint64_t(64) << 32) | (uint64_t(1) << 16);
__device__ __forceinline__ uint64_t make_desc(uint32_t smaddr) {
  return DESC_BASE | ((uint64_t)(smaddr >> 4) & 0x3FFF);
}
// idesc: f32 acc, bf16 x bf16, M=128, N=64, K-major both
static constexpr uint32_t IDESC =
    (1u << 4) | (1u << 7) | (1u << 10) | ((64u >> 3) << 17) | ((128u >> 4) << 24);
#endif  // TC_OK

// blocked SW128 byte offsets (rows x 128 bf16 cols, 8x64 atoms, atom cols stacked)
__device__ __forceinline__ uint32_t wByte(int r, int c) {  // 128-row tile (W~)
  return sw128((uint32_t)((((r >> 3) + (c >> 6) * 16) << 10) + ((r & 7) << 7) + ((c & 63) << 1)));
}
__device__ __forceinline__ uint32_t zByte(int r, int c) {  // 64-row tile (z)
  return sw128((uint32_t)((((r >> 3) + (c >> 6) * 8) << 10) + ((r & 7) << 7) + ((c & 63) << 1)));
}

// ---------------- mask sums ----------------
__global__ void k_masksums(const float* __restrict__ mask) {
  __shared__ float red[2][256];
  int i = blockIdx.x, tid = threadIdx.x;
  float sc = 0.f, sr = 0.f;
  for (int j = tid; j < L; j += 256) {
    sc += mask[(size_t)i * L + j];
    sr += mask[(size_t)j * L + i];
  }
  red[0][tid] = sc; red[1][tid] = sr;
  __syncthreads();
  for (int s = 128; s > 0; s >>= 1) {
    if (tid < s) { red[0][tid] += red[0][tid + s]; red[1][tid] += red[1][tid + s]; }
    __syncthreads();
  }
  if (tid == 0) { g_maskC[i] = red[0][0]; g_maskR[i] = red[1][0]; }
}

// ---------------- prep ----------------
__global__ void k_prep(const float* __restrict__ w1, const float* __restrict__ b1,
                       const float* __restrict__ ln_g, const float* __restrict__ ln_b) {
  int d = threadIdx.x;
  float u = b1[d], v = 0.f;
  for (int c = 0; c < CZ; c++) {
    float w = w1[d * CZ + c];
    u += ln_b[c] * w;
    v += ln_g[c] * w;
  }
  g_u[d] = u; g_v[d] = v;
}

// ---------------- stage 1: tcgen05 D[d,pair] = W~ @ z^T, 512 threads ----------------
__global__ __launch_bounds__(512, 1) void k_stage1(
    const float* __restrict__ s_z, const float* __restrict__ mask,
    const float* __restrict__ ln_g, const float* __restrict__ w1) {
#if TC_OK
  extern __shared__ char smem_raw[];
  __nv_bfloat16* sW  = (__nv_bfloat16*)smem_raw;            // 32768  W~ blocked
  __nv_bfloat16* sZb = (__nv_bfloat16*)(smem_raw + 32768);  // 2x16384 z bf16 blocked
  float* sZf   = (float*)(smem_raw + 65536);                // 2x(64*132*4)=67584 staging
  float* sMaskT= (float*)(smem_raw + 133120);               // [128 m][68 l] = 34816
  float* sS    = (float*)(smem_raw + 167936);               // 2048
  float* sS2   = (float*)(smem_raw + 169984);               // 2048
  float* sRsMu = (float*)(smem_raw + 172032);               // [2][64][2] = 1024
  float* sRowP = (float*)(smem_raw + 173056);               // [2][4][128] = 4096
  uint32_t* sT = (uint32_t*)(smem_raw + 177152);
  const uint32_t mbarA[2] = { smem_u32(smem_raw + 177160), smem_u32(smem_raw + 177168) };

  const int tid = threadIdx.x, lane = tid & 31, warp = tid >> 5;
  const int bx = blockIdx.x, by = blockIdx.y;
  const int m0 = bx * 128, l0 = by * 64;
  const int dsub = warp & 3, q4 = warp >> 2;    // subpartition / column quarter
  const int dd = dsub * 32 + lane;              // this thread's output channel

  const uint32_t zfB = smem_u32(sZf);

  // ---- init ----
  if (warp == 0) { TC_ALLOC(smem_u32(sT), 128); TC_RELINQ(); }
  if (tid == 0) { MBAR_INIT(mbarA[0], 1); MBAR_INIT(mbarA[1], 1); }
  for (int i = tid; i < 128 * 128; i += 512) {
    int d = i >> 7, c = i & 127;
    *(__nv_bfloat16*)((char*)sW + wByte(d, c)) = __float2bfloat16(w1[i] * ln_g[c]);
  }
  // mask tile transposed: sMaskT[m][l], stride 68
  for (int i = tid; i < 64 * 32; i += 512) {
    int r = i >> 5, c4 = (i & 31) << 2;
    float4 mv = *(const float4*)(mask + (size_t)(l0 + r) * L + m0 + c4);
    sMaskT[(c4 + 0) * 68 + r] = mv.x;
    sMaskT[(c4 + 1) * 68 + r] = mv.y;
    sMaskT[(c4 + 2) * 68 + r] = mv.z;
    sMaskT[(c4 + 3) * 68 + r] = mv.w;
  }
  const float uD = g_u[dd], vD = g_v[dd];
  __syncthreads();
  const uint32_t tmem = sT[0];

  // ---- COALESCED staging issue: warp covers rows 4w..4w+3; instruction j reads
  //      one FULL row (32 lanes x 16B = 512B contiguous = 4 complete 128B lines).
  //      Wavefronts/pass: 64 rows x 4 lines = 256 (was 2048 with row-per-lane).
  auto issue = [&](int mi, int buf) {
    #pragma unroll
    for (int j = 0; j < 4; j++) {
      const int row = warp * 4 + j;
      const float* src = s_z + ((size_t)(l0 + row) * L + (m0 + mi)) * CZ + lane * 4;
      uint32_t dst = zfB + (uint32_t)((buf * 64 * 132 + row * 132 + lane * 4) * 4);
      cp16(dst, src);
    }
    cp_commit();
  };

  // pack/stat consumption mapping (unchanged): thread-local 16-float row chunks
  const int prow = (warp >> 3) * 32 + lane, pseg = warp & 7;

  float colAcc[16];
  #pragma unroll
  for (int j = 0; j < 16; j++) colAcc[j] = 0.f;

  const uint64_t wDesc = make_desc(smem_u32(sW));

  // epilogue for pass pj (D in buffer pb); accumulates colAcc, writes sRowP
  auto epilogue = [&](int pj, int pb) {
    mbar_wait(mbarA[pb], (uint32_t)((pj >> 1) & 1));
    TC_FENCE_A();
    uint32_t dr[16];
    ldtm_x16(dr, tmem + pb * 64 + q4 * 16);
    TC_WAIT_LD();
    float rsum = 0.f;
    #pragma unroll
    for (int h2 = 0; h2 < 2; h2++) {
      float4 rm[4];
      #pragma unroll
      for (int k = 0; k < 4; k++)
        rm[k] = *(const float4*)(sRsMu + (pb * 64 + q4 * 16 + h2 * 8) * 2 + k * 4);
      float4 mk0 = *(const float4*)(sMaskT + pj * 68 + q4 * 16 + h2 * 8);
      float4 mk1 = *(const float4*)(sMaskT + pj * 68 + q4 * 16 + h2 * 8 + 4);
      const float* rmf = (const float*)rm;
      #pragma unroll
      for (int j = 0; j < 8; j++) {
        float rs   = rmf[2 * j];
        float murs = rmf[2 * j + 1];
        float mk   = (j < 4) ? ((const float*)&mk0)[j] : ((const float*)&mk1)[j - 4];
        float h = fmaf(rs, __uint_as_float(dr[h2 * 8 + j]), fmaf(murs, vD, uD));
        h = fmaxf(h, 0.f) * mk;
        colAcc[h2 * 8 + j] += h;
        rsum += h;
      }
    }
    sRowP[(pj & 1) * 512 + q4 * 128 + dd] = rsum;
    TC_FENCE_B();
  };
  // combine quarter row-sums of pass p -> g_PartR (after a barrier covering sRowP writes)
  auto combine = [&](int p) {
    if (tid < 128) {
      const float* rp = sRowP + (p & 1) * 512;
      float v = rp[tid] + rp[128 + tid] + rp[256 + tid] + rp[384 + tid];
      g_PartR[((size_t)by * L + (m0 + p)) * CZ + tid] = v;
    }
  };

  issue(0, 0);

  for (int mi = 0; mi < 128; mi++) {
    const int buf = mi & 1;
    if (mi < 127) {
      issue(mi + 1, buf ^ 1);
      asm volatile("cp.async.wait_group 1;");
    } else {
      asm volatile("cp.async.wait_group 0;");
    }
    __syncthreads();  // barA: staging[buf] ready; sRowP[mi&1] (pass mi-2) complete

    if (mi >= 2) combine(mi - 2);

    // ---- pack fp32 -> bf16 blocked/swizzled + stat partials ----
    {
      const float* zr = sZf + buf * (64 * 132) + prow * 132 + pseg * 16;
      char* zbB = (char*)(sZb + buf * (64 * 128));
      float4 v0 = *(const float4*)(zr);
      float4 v1 = *(const float4*)(zr + 4);
      float4 v2 = *(const float4*)(zr + 8);
      float4 v3 = *(const float4*)(zr + 12);
      __nv_bfloat162 p0 = __floats2bfloat162_rn(v0.x, v0.y);
      __nv_bfloat162 p1 = __floats2bfloat162_rn(v0.z, v0.w);
      __nv_bfloat162 p2 = __floats2bfloat162_rn(v1.x, v1.y);
      __nv_bfloat162 p3 = __floats2bfloat162_rn(v1.z, v1.w);
      __nv_bfloat162 p4 = __floats2bfloat162_rn(v2.x, v2.y);
      __nv_bfloat162 p5 = __floats2bfloat162_rn(v2.z, v2.w);
      __nv_bfloat162 p6 = __floats2bfloat162_rn(v3.x, v3.y);
      __nv_bfloat162 p7 = __floats2bfloat162_rn(v3.z, v3.w);
      *(uint4*)(zbB + zByte(prow, pseg * 16)) =
          make_uint4(*(uint32_t*)&p0, *(uint32_t*)&p1, *(uint32_t*)&p2, *(uint32_t*)&p3);
      *(uint4*)(zbB + zByte(prow, pseg * 16 + 8)) =
          make_uint4(*(uint32_t*)&p4, *(uint32_t*)&p5, *(uint32_t*)&p6, *(uint32_t*)&p7);
      float s  = (v0.x + v0.y + v0.z + v0.w) + (v1.x + v1.y + v1.z + v1.w)
               + (v2.x + v2.y + v2.z + v2.w) + (v3.x + v3.y + v3.z + v3.w);
      float s2 = (v0.x*v0.x + v0.y*v0.y + v0.z*v0.z + v0.w*v0.w)
               + (v1.x*v1.x + v1.y*v1.y + v1.z*v1.z + v1.w*v1.w)
               + (v2.x*v2.x + v2.y*v2.y + v2.z*v2.z + v2.w*v2.w)
               + (v3.x*v3.x + v3.y*v3.y + v3.z*v3.z + v3.w*v3.w);
      sS[tid] = s; sS2[tid] = s2;
      TC_FENCE_B();
    }
    __syncthreads();  // barB: zb[buf], partials ready

    // stat combine -> sRsMu[buf]
    if (tid < 64) {
      const int base = (tid >> 5) * 256 + (tid & 31);
      float s = 0.f, s2 = 0.f;
      #pragma unroll
      for (int sg = 0; sg < 8; sg++) { s += sS[base + sg * 32]; s2 += sS2[base + sg * 32]; }
      float mu  = s * (1.f / 128.f);
      float var = fmaf(s2, 1.f / 128.f, -mu * mu);
      float rs  = rsqrtf(var + 1e-5f);
      sRsMu[(buf * 64 + tid) * 2]     = rs;
      sRsMu[(buf * 64 + tid) * 2 + 1] = -mu * rs;
    }

    // ---- issue MMA(mi) into D[buf] ----
    if (warp == 0) {
      TC_FENCE_A();
      if (elect1()) {
        uint64_t zDesc = make_desc(smem_u32(sZb + buf * (64 * 128)));
        #pragma unroll
        for (int kc = 0; kc < 8; kc++) {
          uint64_t aOff = (uint64_t)((kc & 3) * 2 + (kc >> 2) * 1024);
          uint64_t bOff = (uint64_t)((kc & 3) * 2 + (kc >> 2) * 512);
          mma_f16_ss(tmem + buf * 64, wDesc + aOff, zDesc + bOff, IDESC, kc > 0);
        }
        TC_COMMIT(mbarA[buf]);
      }
    }

    // ---- epilogue for pass mi-1 ----
    if (mi > 0) epilogue(mi - 1, buf ^ 1);
  }

  __syncthreads();
  combine(126);
  epilogue(127, 1);
  __syncthreads();
  combine(127);

  // ---- write column partials: slot = bx; thread owns l = q4*16+j ----
  #pragma unroll
  for (int j = 0; j < 16; j++) {
    int l = l0 + q4 * 16 + j;
    g_PartC[((size_t)bx * L + l) * CZ + dd] = colAcc[j];
  }

  __syncthreads();
  if (warp == 0) TC_DEALLOC(tmem, 128);

#else  // ---------------- fallback (generic PTX target only; correct, slow) ----------------
  extern __shared__ char smem_raw[];
  float* sWf  = (float*)smem_raw;             // [128][128] fp32 W~
  float* sZ1  = (float*)(smem_raw + 65536);   // [64][128]
  float* sSt  = (float*)(smem_raw + 98304);   // [64][2]
  float* sRp  = (float*)(smem_raw + 99328);   // [4][128]

  const int tid = threadIdx.x;
  const int bx = blockIdx.x, by = blockIdx.y;
  const int m0 = bx * 128, l0 = by * 64;
  const int d = tid & 127, grp = tid >> 7;    // 4 groups of 16 l's

  for (int i = tid; i < 128 * 128; i += 512) {
    int c = i & 127;
    sWf[i] = w1[i] * ln_g[c];
  }
  const float uD = g_u[d], vD = g_v[d];
  float colAcc[16];
  #pragma unroll
  for (int j = 0; j < 16; j++) colAcc[j] = 0.f;
  __syncthreads();

  for (int mi = 0; mi < 128; mi++) {
    for (int i = tid; i < 64 * 32; i += 512) {
      int r = i >> 5, c4 = (i & 31) << 2;
      float4 v = *(const float4*)(s_z + ((size_t)(l0 + r) * L + (m0 + mi)) * CZ + c4);
      *(float4*)(sZ1 + r * 128 + c4) = v;
    }
    __syncthreads();
    if (tid < 64) {
      float s = 0.f, s2 = 0.f;
      for (int c = 0; c < 128; c++) {
        float v = sZ1[tid * 128 + c];
        s += v; s2 += v * v;
      }
      float mu  = s * (1.f / 128.f);
      float var = fmaf(s2, 1.f / 128.f, -mu * mu);
      float rs  = rsqrtf(var + 1e-5f);
      sSt[tid * 2] = rs; sSt[tid * 2 + 1] = -mu * rs;
    }
    __syncthreads();
    float rsum = 0.f;
    for (int j = 0; j < 16; j++) {
      int l = grp * 16 + j;
      float dot = 0.f;
      for (int c = 0; c < 128; c++)
        dot = fmaf(__bfloat162float(__float2bfloat16(sZ1[l * 128 + c])),
                   __bfloat162float(__float2bfloat16(sWf[d * 128 + c])), dot);
      float h = fmaf(sSt[l * 2], dot, fmaf(sSt[l * 2 + 1], vD, uD));
      h = fmaxf(h, 0.f) * mask[(size_t)(l0 + l) * L + (m0 + mi)];
      colAcc[j] += h; rsum += h;
    }
    sRp[grp * 128 + d] = rsum;
    __syncthreads();
    if (tid < 128)
      g_PartR[((size_t)by * L + (m0 + mi)) * CZ + tid] =
          sRp[tid] + sRp[128 + tid] + sRp[256 + tid] + sRp[384 + tid];
    __syncthreads();
  }
  for (int j = 0; j < 16; j++)
    g_PartC[((size_t)bx * L + (l0 + grp * 16 + j)) * CZ + d] = colAcc[j];
#endif
}

// ---------------- stage 2 ----------------
__global__ __launch_bounds__(256) void k_stage2(const float* __restrict__ w2,
                                                const float* __restrict__ b2) {
  extern __shared__ float w2s[];          // [128][132]
  __shared__ float sv[2][128];
  const int tid = threadIdx.x;
  const int half = tid >> 7, d = tid & 127;

  for (int i = tid; i < 128 * 128; i += 256) {
    int r = i >> 7, c = i & 127;
    w2s[r * 132 + c] = w2[i];
  }
  const float bd = b2[d];
  const float* P = half ? g_PartR : g_PartC;
  float* O = half ? g_ssr : g_ssc;
  const float* M = half ? g_maskR : g_maskC;
  const int nsl = half ? NTR : NTC;
  __syncthreads();

  for (int ii = 0; ii < 2; ii++) {
    const int i = blockIdx.x * 2 + ii;
    float a = 0.f;
    for (int t = 0; t < nsl; t++) a += P[((size_t)t * L + i) * CZ + d];
    if (ii) __syncthreads();
    sv[half][d] = a;
    __syncthreads();
    float m = M[i];
    const float4* wr = (const float4*)(w2s + d * 132);
    const float4* s4 = (const float4*)sv[half];
    float d0 = 0.f, d1 = 0.f, d2 = 0.f, d3 = 0.f;
    #pragma unroll
    for (int c = 0; c < 32; c++) {
      float4 wv = wr[c];
      float4 vv = s4[c];
      d0 = fmaf(vv.x, wv.x, d0);
      d1 = fmaf(vv.y, wv.y, d1);
      d2 = fmaf(vv.z, wv.z, d2);
      d3 = fmaf(vv.w, wv.w, d3);
    }
    O[i * CZ + d] = ((d0 + d1) + (d2 + d3) + bd * m) / fmaxf(m, 1.f);
  }
}

// ---------------- stage 3: out = cat @ wc^T + bc, tf32, pipelined ----------------
__global__ __launch_bounds__(256) void k_stage3(
    const float* __restrict__ s_s_in, const float* __restrict__ wc,
    const float* __restrict__ bc, float* __restrict__ out) {
  extern __shared__ float sm3[];
  float* sA3 = sm3;                 // [2][64][68]
  float* sB3 = sm3 + 2 * 64 * 68;   // [2][64][68]
  const uint32_t aBase = smem_u32(sA3);
  const uint32_t bBase = smem_u32(sB3);

  const int tid = threadIdx.x, lane = tid & 31, warp = tid >> 5;
  const int g = lane >> 2, q = lane & 3;
  const int wm = warp >> 1, wn = warp & 1;
  const int d0 = blockIdx.x * 64, t0 = blockIdx.y * 64;

  const int cr = tid >> 2, cseg = tid & 3;

  auto issue = [&](int kc, int buf) {
    const float* srcA; int strideA, koffA;
    if (kc < 2)      { srcA = g_ssc;  strideA = 128;  koffA = kc * 64; }
    else if (kc < 4) { srcA = g_ssr;  strideA = 128;  koffA = (kc - 2) * 64; }
    else             { srcA = s_s_in; strideA = 1024; koffA = (kc - 4) * 64; }
    const float* sa = srcA + (size_t)(t0 + cr) * strideA + koffA + cseg * 16;
    const float* sb = wc + (size_t)(d0 + cr) * 1280 + kc * 64 + cseg * 16;
    uint32_t da = aBase + (uint32_t)(buf * 4352 + cr * 68 + cseg * 16) * 4;
    uint32_t db = bBase + (uint32_t)(buf * 4352 + cr * 68 + cseg * 16) * 4;
    #pragma unroll
    for (int j = 0; j < 4; j++) { cp16(da + j * 16, sa + j * 4); cp16(db + j * 16, sb + j * 4); }
    cp_commit();
  };

  float acc[4][4];
  #pragma unroll
  for (int b = 0; b < 4; b++)
    #pragma unroll
    for (int c = 0; c < 4; c++) acc[b][c] = 0.f;

  issue(0, 0);

  for (int kc = 0; kc < 20; kc++) {
    const int buf = kc & 1;
    if (kc + 1 < 20) {
      issue(kc + 1, buf ^ 1);
      asm volatile("cp.async.wait_group 1;");
    } else {
      asm volatile("cp.async.wait_group 0;");
    }
    __syncthreads();

    const float* A = sA3 + buf * 4352;
    const float* B = sB3 + buf * 4352;
    const int R = wm * 16;
    #pragma unroll
    for (int ks = 0; ks < 8; ks++) {
      const int k0 = ks * 8;
      uint32_t a0 = f2tf(A[(R + g    ) * 68 + k0 + q    ]);
      uint32_t a1 = f2tf(A[(R + g + 8) * 68 + k0 + q    ]);
      uint32_t a2 = f2tf(A[(R + g    ) * 68 + k0 + q + 4]);
      uint32_t a3 = f2tf(A[(R + g + 8) * 68 + k0 + q + 4]);
      #pragma unroll
      for (int nb = 0; nb < 4; nb++) {
        const int n = wn * 32 + nb * 8 + g;
        uint32_t b0 = f2tf(B[n * 68 + k0 + q    ]);
        uint32_t b1 = f2tf(B[n * 68 + k0 + q + 4]);
        asm volatile(
          "mma.sync.aligned.m16n8k8.row.col.f32.tf32.tf32.f32 "
          "{%0,%1,%2,%3}, {%4,%5,%6,%7}, {%8,%9}, {%0,%1,%2,%3};\n"
          : "+f"(acc[nb][0]), "+f"(acc[nb][1]), "+f"(acc[nb][2]), "+f"(acc[nb][3])
          : "r"(a0), "r"(a1), "r"(a2), "r"(a3), "r"(b0), "r"(b1));
      }
    }
    __syncthreads();
  }

  const int r0 = t0 + wm * 16 + g;
  #pragma unroll
  for (int nb = 0; nb < 4; nb++) {
    const int c = d0 + wn * 32 + nb * 8 + q * 2;
    float bc0 = bc[c], bc1 = bc[c + 1];
    *(float2*)(out + (size_t)r0 * L + c)       = make_float2(acc[nb][0] + bc0, acc[nb][1] + bc1);
    *(float2*)(out + (size_t)(r0 + 8) * L + c) = make_float2(acc[nb][2] + bc0, acc[nb][3] + bc1);
  }
}

// ---------------- launch ----------------
extern "C" void kernel_launch(void* const* d_in, const int* in_sizes, int n_in,
                              void* d_out, int out_size) {
  const float* s_z    = (const float*)d_in[0];
  const float* s_s_in = (const float*)d_in[1];
  const float* pmask  = (const float*)d_in[2];
  const float* ln_g   = (const float*)d_in[3];
  const float* ln_b   = (const float*)d_in[4];
  const float* w1     = (const float*)d_in[5];
  const float* b1     = (const float*)d_in[6];
  const float* w2     = (const float*)d_in[7];
  const float* b2     = (const float*)d_in[8];
  const float* wc     = (const float*)d_in[9];
  const float* bc     = (const float*)d_in[10];
  float* out = (float*)d_out;

  const int smem1 = 177280;
  const int smem2 = 128 * 132 * 4;        // 67584
  const int smem3 = 2 * 2 * 64 * 68 * 4;  // 69632
  cudaFuncSetAttribute(k_stage1, cudaFuncAttributeMaxDynamicSharedMemorySize, smem1);
  cudaFuncSetAttribute(k_stage2, cudaFuncAttributeMaxDynamicSharedMemorySize, smem2);
  cudaFuncSetAttribute(k_stage3, cudaFuncAttributeMaxDynamicSharedMemorySize, smem3);

  k_masksums<<<L, 256>>>(pmask);
  k_prep<<<1, CZ>>>(w1, b1, ln_g, ln_b);
  k_stage1<<<dim3(8, 16), 512, smem1>>>(s_z, pmask, ln_g, w1);
  k_stage2<<<512, 256, smem2>>>(w2, b2);
  k_stage3<<<dim3(16, 16), 256, smem3>>>(s_s_in, wc, bc, out);
}